// round 7
// baseline (speedup 1.0000x reference)
#include <cuda_runtime.h>
#include <cuda_bf16.h>
#include <cstdint>

// Shapes
#define B_  2
#define L_  8192
#define G_  256
#define DG_ 8
#define D_  2048          // G_*DG_
#define NFFT 16384        // 2*L_, power of 4 (4^7)
#define NBFLY (NFFT/4)    // 4096 butterflies per radix-4 stage
#define TPB 512
#define TWN  (NFFT/4)     // quarter-circle twiddle table, 4096 entries

// skewed smem index to break power-of-2 bank-conflict strides
__device__ __forceinline__ int phys(int i) { return i + (i >> 5); }

#define SMEM_F2 (NFFT + NFFT/32 + TWN)         // 16896 + 4096 = 20992 float2
#define SMEM_BYTES (SMEM_F2 * (int)sizeof(float2))  // 167936 B

// scratch (device globals: allocation-free)
__device__ float  g_kvT[(size_t)B_ * D_ * L_];   // (B, D, L) kv = x2*v
__device__ float  g_yT [(size_t)B_ * D_ * L_];   // (B, D, L) conv output
__device__ float2 g_HF [(size_t)G_ * NFFT];      // per-group filter spectrum (scrambled, scaled 1/N)

__device__ __forceinline__ float2 cmul(float2 a, float2 b) {
    return make_float2(a.x * b.x - a.y * b.y, a.x * b.y + a.y * b.x);
}

// build quarter-circle twiddle table: TW[k] = e^{-2*pi*i*k/NFFT}, k in [0, TWN)
__device__ __forceinline__ void build_tw(float2* TW, int tid) {
    for (int k = tid; k < TWN; k += TPB) {
        float s, c;
        // angle = -2*pi*k/NFFT  -> sincospi arg = -2k/NFFT = -k/8192
        sincospif(-(float)k * (1.0f / (NFFT / 2)), &s, &c);
        TW[k] = make_float2(c, s);
    }
}

// radix-4 DIF forward, in place, natural in -> digit-reversed out
__device__ void fft_fwd(float2* S, const float2* TW, int tid) {
    #pragma unroll
    for (int L = NFFT; L >= 4; L >>= 2) {
        const int q = L >> 2;
        const int tmul = NFFT / L;
        for (int b = tid; b < NBFLY; b += TPB) {
            int j  = b & (q - 1);
            int i0 = 4 * b - 3 * j;           // = (b/q)*L + j
            float2 a0 = S[phys(i0)];
            float2 a1 = S[phys(i0 + q)];
            float2 a2 = S[phys(i0 + 2 * q)];
            float2 a3 = S[phys(i0 + 3 * q)];
            float2 t0 = make_float2(a0.x + a2.x, a0.y + a2.y);
            float2 t1 = make_float2(a0.x - a2.x, a0.y - a2.y);
            float2 t2 = make_float2(a1.x + a3.x, a1.y + a3.y);
            float2 t3 = make_float2(a1.x - a3.x, a1.y - a3.y);
            float2 y0 = make_float2(t0.x + t2.x, t0.y + t2.y);
            float2 y2 = make_float2(t0.x - t2.x, t0.y - t2.y);
            float2 y1 = make_float2(t1.x + t3.y, t1.y - t3.x);   // t1 - i t3
            float2 y3 = make_float2(t1.x - t3.y, t1.y + t3.x);   // t1 + i t3
            float2 w1 = TW[j * tmul];
            float2 w2 = cmul(w1, w1);
            float2 w3 = cmul(w2, w1);
            S[phys(i0)]         = y0;
            S[phys(i0 + q)]     = cmul(y1, w1);
            S[phys(i0 + 2 * q)] = cmul(y2, w2);
            S[phys(i0 + 3 * q)] = cmul(y3, w3);
        }
        __syncthreads();
    }
}

// radix-4 DIT inverse (unscaled: produces NFFT * IDFT), digit-reversed in -> natural out
__device__ void fft_inv(float2* S, const float2* TW, int tid) {
    #pragma unroll
    for (int L = 4; L <= NFFT; L <<= 2) {
        const int q = L >> 2;
        const int tmul = NFFT / L;
        for (int b = tid; b < NBFLY; b += TPB) {
            int j  = b & (q - 1);
            int i0 = 4 * b - 3 * j;
            float2 c0 = S[phys(i0)];
            float2 c1 = S[phys(i0 + q)];
            float2 c2 = S[phys(i0 + 2 * q)];
            float2 c3 = S[phys(i0 + 3 * q)];
            float2 wf = TW[j * tmul];
            float2 w1 = make_float2(wf.x, -wf.y);      // conj -> e^{+i...}
            float2 w2 = cmul(w1, w1);
            float2 w3 = cmul(w2, w1);
            float2 d1 = cmul(c1, w1);
            float2 d2 = cmul(c2, w2);
            float2 d3 = cmul(c3, w3);
            float2 u0 = make_float2(c0.x + d2.x, c0.y + d2.y);
            float2 u1 = make_float2(c0.x - d2.x, c0.y - d2.y);
            float2 u2 = make_float2(d1.x + d3.x, d1.y + d3.y);
            float2 u3 = make_float2(d1.x - d3.x, d1.y - d3.y);
            S[phys(i0)]         = make_float2(u0.x + u2.x, u0.y + u2.y);
            S[phys(i0 + 2 * q)] = make_float2(u0.x - u2.x, u0.y - u2.y);
            S[phys(i0 + q)]     = make_float2(u1.x - u3.y, u1.y + u3.x);  // u1 + i u3
            S[phys(i0 + 3 * q)] = make_float2(u1.x + u3.y, u1.y - u3.x);  // u1 - i u3
        }
        __syncthreads();
    }
}

// K0: filter spectrum per group. grid = G_, block = TPB
__global__ void __launch_bounds__(TPB, 1)
filter_fft_kernel(const float* __restrict__ h) {
    extern __shared__ float2 smem[];
    float2* S  = smem;
    float2* TW = smem + (NFFT + NFFT / 32);
    const int tid = threadIdx.x;
    const int g = blockIdx.x;
    build_tw(TW, tid);
    const float* hr = h + (size_t)g * L_;
    for (int i = tid; i < L_; i += TPB)    S[phys(i)] = make_float2(hr[i], 0.0f);
    for (int i = L_ + tid; i < NFFT; i += TPB) S[phys(i)] = make_float2(0.0f, 0.0f);
    __syncthreads();
    fft_fwd(S, TW, tid);
    const float sc = 1.0f / (float)NFFT;   // fold IFFT scale into filter spectrum
    float2* out = g_HF + (size_t)g * NFFT;
    for (int k = tid; k < NFFT; k += TPB) {
        float2 v = S[phys(k)];
        out[k] = make_float2(v.x * sc, v.y * sc);
    }
}

// K1: kvT[b,c,l] = x2[b,l,c] * v[b,l,c]. grid (D/32, L/32, B), block (32,8)
__global__ void kv_transpose_kernel(const float* __restrict__ x2,
                                    const float* __restrict__ v) {
    __shared__ float tile[32][33];
    const int tx = threadIdx.x, ty = threadIdx.y;
    const int c0 = blockIdx.x * 32, l0 = blockIdx.y * 32, b = blockIdx.z;
    #pragma unroll
    for (int k = 0; k < 4; k++) {
        int l = l0 + ty + k * 8;
        size_t idx = ((size_t)(b * L_ + l)) * D_ + (c0 + tx);
        tile[ty + k * 8][tx] = x2[idx] * v[idx];
    }
    __syncthreads();
    #pragma unroll
    for (int k = 0; k < 4; k++) {
        int c = c0 + ty + k * 8;
        int l = l0 + tx;
        g_kvT[((size_t)(b * D_ + c)) * L_ + l] = tile[tx][ty + k * 8];
    }
}

// K2: per (b,c) FFT convolution + bias. grid = B*D, block = TPB
__global__ void __launch_bounds__(TPB, 1)
conv_fft_kernel(const float* __restrict__ conv_bias) {
    extern __shared__ float2 smem[];
    float2* S  = smem;
    float2* TW = smem + (NFFT + NFFT / 32);
    const int tid = threadIdx.x;
    const int row = blockIdx.x;          // = b*D_ + c
    const int c   = row & (D_ - 1);
    const int g   = c >> 3;              // c / DG_
    build_tw(TW, tid);
    const float* kv = g_kvT + (size_t)row * L_;
    for (int i = tid; i < L_; i += TPB)        S[phys(i)] = make_float2(kv[i], 0.0f);
    for (int i = L_ + tid; i < NFFT; i += TPB) S[phys(i)] = make_float2(0.0f, 0.0f);
    __syncthreads();
    fft_fwd(S, TW, tid);
    const float2* HF = g_HF + (size_t)g * NFFT;
    for (int k = tid; k < NFFT; k += TPB) {
        S[phys(k)] = cmul(S[phys(k)], __ldg(&HF[k]));
    }
    __syncthreads();
    fft_inv(S, TW, tid);
    const float bias = conv_bias[c];
    float* out = g_yT + (size_t)row * L_;
    for (int i = tid; i < L_; i += TPB) {
        out[i] = S[phys(i)].x + kv[i] * bias;
    }
}

// K3: out[b,l,c] = x1[b,l,c] * yT[b,c,l]. grid (D/32, L/32, B), block (32,8)
__global__ void gate_transpose_kernel(const float* __restrict__ x1,
                                      float* __restrict__ out) {
    __shared__ float tile[32][33];
    const int tx = threadIdx.x, ty = threadIdx.y;
    const int c0 = blockIdx.x * 32, l0 = blockIdx.y * 32, b = blockIdx.z;
    #pragma unroll
    for (int k = 0; k < 4; k++) {
        int c = c0 + ty + k * 8;
        int l = l0 + tx;
        tile[ty + k * 8][tx] = g_yT[((size_t)(b * D_ + c)) * L_ + l];
    }
    __syncthreads();
    #pragma unroll
    for (int k = 0; k < 4; k++) {
        int l = l0 + ty + k * 8;
        size_t idx = ((size_t)(b * L_ + l)) * D_ + (c0 + tx);
        out[idx] = x1[idx] * tile[tx][ty + k * 8];
    }
}

extern "C" void kernel_launch(void* const* d_in, const int* in_sizes, int n_in,
                              void* d_out, int out_size) {
    const float* x1   = (const float*)d_in[0];
    const float* x2   = (const float*)d_in[1];
    const float* v    = (const float*)d_in[2];
    const float* h    = (const float*)d_in[3];
    const float* bias = (const float*)d_in[4];
    float* out = (float*)d_out;

    cudaFuncSetAttribute(filter_fft_kernel,
                         cudaFuncAttributeMaxDynamicSharedMemorySize, SMEM_BYTES);
    cudaFuncSetAttribute(conv_fft_kernel,
                         cudaFuncAttributeMaxDynamicSharedMemorySize, SMEM_BYTES);

    dim3 tgrid(D_ / 32, L_ / 32, B_);
    dim3 tblk(32, 8);

    filter_fft_kernel<<<G_, TPB, SMEM_BYTES>>>(h);
    kv_transpose_kernel<<<tgrid, tblk>>>(x2, v);
    conv_fft_kernel<<<B_ * D_, TPB, SMEM_BYTES>>>(bias);
    gate_transpose_kernel<<<tgrid, tblk>>>(x1, out);
}

// round 9
// speedup vs baseline: 1.7948x; 1.7948x over previous
#include <cuda_runtime.h>
#include <cuda_bf16.h>
#include <cstdint>

// Shapes
#define B_  2
#define L_  8192
#define G_  256
#define DG_ 8
#define D_  2048          // G_*DG_
#define CP_ (D_/2)        // 1024 channel pairs
#define NFFT 16384        // 2*L_, power of 4 (4^7)
#define NBFLY (NFFT/4)    // 4096 butterflies per radix-4 stage
#define TPB 512
#define TWN  (NFFT/4)     // quarter-circle twiddle table, 4096 entries

// skewed smem index to break power-of-2 bank-conflict strides
__device__ __forceinline__ int phys(int i) { return i + (i >> 5); }

#define SMEM_F2 (NFFT + NFFT/32 + TWN)              // 16896 + 4096 = 20992 float2
#define SMEM_BYTES (SMEM_F2 * (int)sizeof(float2))  // 167936 B

// scratch (device globals: allocation-free)
__device__ float2 g_kvP[(size_t)B_ * CP_ * L_];   // (B, CP, L) packed kv pairs
__device__ float2 g_yP [(size_t)B_ * CP_ * L_];   // (B, CP, L) packed conv output pairs
__device__ float2 g_HF [(size_t)G_ * NFFT];       // per-group filter spectrum (scrambled, /N)
__device__ float2 g_TW [TWN];                     // twiddle table (global master copy)

__device__ __forceinline__ float2 cmul(float2 a, float2 b) {
    return make_float2(a.x * b.x - a.y * b.y, a.x * b.y + a.y * b.x);
}

// K-1: build twiddle table once. TW[k] = e^{-2*pi*i*k/NFFT}
__global__ void twiddle_kernel() {
    int k = blockIdx.x * blockDim.x + threadIdx.x;
    if (k < TWN) {
        float s, c;
        sincospif(-(float)k * (1.0f / (NFFT / 2)), &s, &c);
        g_TW[k] = make_float2(c, s);
    }
}

__device__ __forceinline__ void load_tw(float2* TW, int tid) {
    for (int k = tid; k < TWN; k += TPB) TW[k] = g_TW[k];
}

// radix-4 DIF forward, in place, natural in -> digit-reversed out
__device__ void fft_fwd(float2* S, const float2* TW, int tid) {
    #pragma unroll
    for (int L = NFFT; L >= 4; L >>= 2) {
        const int q = L >> 2;
        const int tmul = NFFT / L;
        for (int b = tid; b < NBFLY; b += TPB) {
            int j  = b & (q - 1);
            int i0 = 4 * b - 3 * j;           // = (b/q)*L + j
            float2 a0 = S[phys(i0)];
            float2 a1 = S[phys(i0 + q)];
            float2 a2 = S[phys(i0 + 2 * q)];
            float2 a3 = S[phys(i0 + 3 * q)];
            float2 t0 = make_float2(a0.x + a2.x, a0.y + a2.y);
            float2 t1 = make_float2(a0.x - a2.x, a0.y - a2.y);
            float2 t2 = make_float2(a1.x + a3.x, a1.y + a3.y);
            float2 t3 = make_float2(a1.x - a3.x, a1.y - a3.y);
            float2 y0 = make_float2(t0.x + t2.x, t0.y + t2.y);
            float2 y2 = make_float2(t0.x - t2.x, t0.y - t2.y);
            float2 y1 = make_float2(t1.x + t3.y, t1.y - t3.x);   // t1 - i t3
            float2 y3 = make_float2(t1.x - t3.y, t1.y + t3.x);   // t1 + i t3
            float2 w1 = TW[j * tmul];
            float2 w2 = cmul(w1, w1);
            float2 w3 = cmul(w2, w1);
            S[phys(i0)]         = y0;
            S[phys(i0 + q)]     = cmul(y1, w1);
            S[phys(i0 + 2 * q)] = cmul(y2, w2);
            S[phys(i0 + 3 * q)] = cmul(y3, w3);
        }
        __syncthreads();
    }
}

// radix-4 DIT inverse (unscaled), digit-reversed in -> natural out
__device__ void fft_inv(float2* S, const float2* TW, int tid) {
    #pragma unroll
    for (int L = 4; L <= NFFT; L <<= 2) {
        const int q = L >> 2;
        const int tmul = NFFT / L;
        for (int b = tid; b < NBFLY; b += TPB) {
            int j  = b & (q - 1);
            int i0 = 4 * b - 3 * j;
            float2 c0 = S[phys(i0)];
            float2 c1 = S[phys(i0 + q)];
            float2 c2 = S[phys(i0 + 2 * q)];
            float2 c3 = S[phys(i0 + 3 * q)];
            float2 wf = TW[j * tmul];
            float2 w1 = make_float2(wf.x, -wf.y);      // conj -> e^{+i...}
            float2 w2 = cmul(w1, w1);
            float2 w3 = cmul(w2, w1);
            float2 d1 = cmul(c1, w1);
            float2 d2 = cmul(c2, w2);
            float2 d3 = cmul(c3, w3);
            float2 u0 = make_float2(c0.x + d2.x, c0.y + d2.y);
            float2 u1 = make_float2(c0.x - d2.x, c0.y - d2.y);
            float2 u2 = make_float2(d1.x + d3.x, d1.y + d3.y);
            float2 u3 = make_float2(d1.x - d3.x, d1.y - d3.y);
            S[phys(i0)]         = make_float2(u0.x + u2.x, u0.y + u2.y);
            S[phys(i0 + 2 * q)] = make_float2(u0.x - u2.x, u0.y - u2.y);
            S[phys(i0 + q)]     = make_float2(u1.x - u3.y, u1.y + u3.x);  // u1 + i u3
            S[phys(i0 + 3 * q)] = make_float2(u1.x + u3.y, u1.y - u3.x);  // u1 - i u3
        }
        __syncthreads();
    }
}

// K0: filter spectrum per group. grid = G_, block = TPB
__global__ void __launch_bounds__(TPB, 1)
filter_fft_kernel(const float* __restrict__ h) {
    extern __shared__ float2 smem[];
    float2* S  = smem;
    float2* TW = smem + (NFFT + NFFT / 32);
    const int tid = threadIdx.x;
    const int g = blockIdx.x;
    load_tw(TW, tid);
    const float* hr = h + (size_t)g * L_;
    for (int i = tid; i < L_; i += TPB)        S[phys(i)] = make_float2(hr[i], 0.0f);
    for (int i = L_ + tid; i < NFFT; i += TPB) S[phys(i)] = make_float2(0.0f, 0.0f);
    __syncthreads();
    fft_fwd(S, TW, tid);
    const float sc = 1.0f / (float)NFFT;   // fold IFFT scale into filter spectrum
    float2* out = g_HF + (size_t)g * NFFT;
    for (int k = tid; k < NFFT; k += TPB) {
        float2 v = S[phys(k)];
        out[k] = make_float2(v.x * sc, v.y * sc);
    }
}

// K1: kvP[b,cp,l] = (kv[2cp], kv[2cp+1]) with kv = x2*v.
// grid (D/32, L/32, B), block (32,8)
__global__ void kv_transpose_kernel(const float* __restrict__ x2,
                                    const float* __restrict__ v) {
    __shared__ float tile[32][33];           // [l_local][c_local]
    const int tx = threadIdx.x, ty = threadIdx.y;
    const int c0 = blockIdx.x * 32, l0 = blockIdx.y * 32, b = blockIdx.z;
    #pragma unroll
    for (int k = 0; k < 4; k++) {
        int l = l0 + ty + k * 8;
        size_t idx = ((size_t)(b * L_ + l)) * D_ + (c0 + tx);
        tile[ty + k * 8][tx] = x2[idx] * v[idx];
    }
    __syncthreads();
    const int cp0 = blockIdx.x * 16;
    #pragma unroll
    for (int k = 0; k < 2; k++) {
        int u = ty + k * 8;                  // channel-pair local index 0..15
        int l = l0 + tx;
        float2 pr = make_float2(tile[tx][2 * u], tile[tx][2 * u + 1]);
        g_kvP[((size_t)(b * CP_ + cp0 + u)) * L_ + l] = pr;
    }
}

// K2: per (b, channel-pair) packed FFT convolution + bias. grid = B*CP_, block = TPB
__global__ void __launch_bounds__(TPB, 1)
conv_fft_kernel(const float* __restrict__ conv_bias) {
    extern __shared__ float2 smem[];
    float2* S  = smem;
    float2* TW = smem + (NFFT + NFFT / 32);
    const int tid = threadIdx.x;
    const int row = blockIdx.x;              // = b*CP_ + cp
    const int cp  = row & (CP_ - 1);
    const int c0  = cp * 2;
    const int g   = c0 >> 3;                 // both channels of the pair share the group
    load_tw(TW, tid);
    const float2* kv = g_kvP + (size_t)row * L_;
    for (int i = tid; i < L_; i += TPB)        S[phys(i)] = kv[i];
    for (int i = L_ + tid; i < NFFT; i += TPB) S[phys(i)] = make_float2(0.0f, 0.0f);
    __syncthreads();
    fft_fwd(S, TW, tid);
    const float2* HF = g_HF + (size_t)g * NFFT;
    for (int k = tid; k < NFFT; k += TPB) {
        S[phys(k)] = cmul(S[phys(k)], __ldg(&HF[k]));
    }
    __syncthreads();
    fft_inv(S, TW, tid);
    const float bias0 = conv_bias[c0];
    const float bias1 = conv_bias[c0 + 1];
    float2* out = g_yP + (size_t)row * L_;
    for (int i = tid; i < L_; i += TPB) {
        float2 s = S[phys(i)];
        float2 k2 = kv[i];
        out[i] = make_float2(s.x + k2.x * bias0, s.y + k2.y * bias1);
    }
}

// K3: out[b,l,c] = x1[b,l,c] * y[b,c,l]. grid (D/32, L/32, B), block (32,8)
__global__ void gate_transpose_kernel(const float* __restrict__ x1,
                                      float* __restrict__ out) {
    __shared__ float tile[32][33];           // [c_local][l_local]
    const int tx = threadIdx.x, ty = threadIdx.y;
    const int c0 = blockIdx.x * 32, l0 = blockIdx.y * 32, b = blockIdx.z;
    const int cp0 = blockIdx.x * 16;
    #pragma unroll
    for (int k = 0; k < 2; k++) {
        int u = ty + k * 8;                  // channel-pair local index
        int l = l0 + tx;
        float2 yv = g_yP[((size_t)(b * CP_ + cp0 + u)) * L_ + l];
        tile[2 * u][tx]     = yv.x;
        tile[2 * u + 1][tx] = yv.y;
    }
    __syncthreads();
    #pragma unroll
    for (int k = 0; k < 4; k++) {
        int l = l0 + ty + k * 8;
        size_t idx = ((size_t)(b * L_ + l)) * D_ + (c0 + tx);
        out[idx] = x1[idx] * tile[tx][ty + k * 8];
    }
}

extern "C" void kernel_launch(void* const* d_in, const int* in_sizes, int n_in,
                              void* d_out, int out_size) {
    const float* x1   = (const float*)d_in[0];
    const float* x2   = (const float*)d_in[1];
    const float* v    = (const float*)d_in[2];
    const float* h    = (const float*)d_in[3];
    const float* bias = (const float*)d_in[4];
    float* out = (float*)d_out;

    cudaFuncSetAttribute(filter_fft_kernel,
                         cudaFuncAttributeMaxDynamicSharedMemorySize, SMEM_BYTES);
    cudaFuncSetAttribute(conv_fft_kernel,
                         cudaFuncAttributeMaxDynamicSharedMemorySize, SMEM_BYTES);

    dim3 tgrid(D_ / 32, L_ / 32, B_);
    dim3 tblk(32, 8);

    twiddle_kernel<<<TWN / 256, 256>>>();
    filter_fft_kernel<<<G_, TPB, SMEM_BYTES>>>(h);
    kv_transpose_kernel<<<tgrid, tblk>>>(x2, v);
    conv_fft_kernel<<<B_ * CP_, TPB, SMEM_BYTES>>>(bias);
    gate_transpose_kernel<<<tgrid, tblk>>>(x1, out);
}

// round 11
// speedup vs baseline: 2.7546x; 1.5348x over previous
#include <cuda_runtime.h>
#include <cuda_bf16.h>
#include <cstdint>

// Shapes
#define B_  2
#define L_  8192
#define G_  256
#define DG_ 8
#define D_  2048          // G_*DG_
#define CP_ (D_/2)        // 1024 channel pairs
#define NFFT 16384        // 2*L_, 4^7
#define NBFLY (NFFT/4)    // 4096
#define NSETS (NFFT/16)   // 1024 fused radix-16 sets per pass
#define TPB 512
#define TWN  (NFFT/4)     // quarter-circle twiddle table

// skewed smem index for the data array
__device__ __forceinline__ int phys(int i) { return i + (i >> 5); }

#define S_F2   (NFFT + NFFT/32)            // 16896
#define TW_F2  (TWN + TWN/32)              // 4224 (skewed twiddle storage)
#define SMEM_F2 (S_F2 + TW_F2)             // 21120
#define SMEM_BYTES (SMEM_F2 * (int)sizeof(float2))  // 168960 B

// scratch (device globals: allocation-free)
__device__ float2 g_kvP[(size_t)B_ * CP_ * L_];   // (B, CP, L) packed kv pairs
__device__ float2 g_yP [(size_t)B_ * CP_ * L_];   // (B, CP, L) packed conv outputs
__device__ float2 g_HF [(size_t)G_ * NFFT];       // per-group filter spectrum (scrambled, /N)
__device__ float2 g_TW [TWN];                     // twiddle master copy

__device__ __forceinline__ float2 cadd(float2 a, float2 b) { return make_float2(a.x + b.x, a.y + b.y); }
__device__ __forceinline__ float2 csub(float2 a, float2 b) { return make_float2(a.x - b.x, a.y - b.y); }
__device__ __forceinline__ float2 cmul(float2 a, float2 b) {
    return make_float2(a.x * b.x - a.y * b.y, a.x * b.y + a.y * b.x);
}
__device__ __forceinline__ float2 conj2(float2 a) { return make_float2(a.x, -a.y); }

// skewed twiddle read
__device__ __forceinline__ float2 twl(const float2* TW, int k) { return TW[k + (k >> 5)]; }

// K-1: build twiddle table once. TW[k] = e^{-2*pi*i*k/NFFT}
__global__ void twiddle_kernel() {
    int k = blockIdx.x * blockDim.x + threadIdx.x;
    if (k < TWN) {
        float s, c;
        sincospif(-(float)k * (1.0f / (NFFT / 2)), &s, &c);
        g_TW[k] = make_float2(c, s);
    }
}

__device__ __forceinline__ void load_tw(float2* TW, int tid) {
    for (int k = tid; k < TWN; k += TPB) TW[k + (k >> 5)] = g_TW[k];
}

// ---------------- fused forward: two DIF radix-4 stages (L and L/4) per smem pass
template <int Lc>
__device__ __forceinline__ void fwd_fused(float2* S, const float2* TW, int tid) {
    const int st   = Lc / 16;
    const int tmul = NFFT / Lc;
    #pragma unroll
    for (int ss = 0; ss < NSETS / TPB; ss++) {
        int s  = tid + ss * TPB;
        int j  = s & (st - 1);
        int i0 = (s / st) * Lc + j;
        float2 x[16];
        #pragma unroll
        for (int m = 0; m < 16; m++) x[m] = S[phys(i0 + m * st)];
        // stage length Lc (span 4*st): groups {g, g+4, g+8, g+12}
        #pragma unroll
        for (int g = 0; g < 4; g++) {
            float2 a0 = x[g], a1 = x[g + 4], a2 = x[g + 8], a3 = x[g + 12];
            float2 t0 = cadd(a0, a2), t1 = csub(a0, a2);
            float2 t2 = cadd(a1, a3), t3 = csub(a1, a3);
            float2 w1 = twl(TW, (j + g * st) * tmul);
            float2 w2 = cmul(w1, w1), w3 = cmul(w2, w1);
            x[g]      = cadd(t0, t2);
            x[g + 4]  = cmul(make_float2(t1.x + t3.y, t1.y - t3.x), w1);
            x[g + 8]  = cmul(csub(t0, t2), w2);
            x[g + 12] = cmul(make_float2(t1.x - t3.y, t1.y + t3.x), w3);
        }
        // stage length Lc/4 (span st): groups {4r..4r+3}, shared twiddle base j
        {
            float2 w1 = twl(TW, j * tmul * 4);
            float2 w2 = cmul(w1, w1), w3 = cmul(w2, w1);
            #pragma unroll
            for (int r = 0; r < 4; r++) {
                float2 a0 = x[4 * r], a1 = x[4 * r + 1], a2 = x[4 * r + 2], a3 = x[4 * r + 3];
                float2 t0 = cadd(a0, a2), t1 = csub(a0, a2);
                float2 t2 = cadd(a1, a3), t3 = csub(a1, a3);
                x[4 * r]     = cadd(t0, t2);
                x[4 * r + 1] = cmul(make_float2(t1.x + t3.y, t1.y - t3.x), w1);
                x[4 * r + 2] = cmul(csub(t0, t2), w2);
                x[4 * r + 3] = cmul(make_float2(t1.x - t3.y, t1.y + t3.x), w3);
            }
        }
        #pragma unroll
        for (int m = 0; m < 16; m++) S[phys(i0 + m * st)] = x[m];
    }
}

// forward: fused (16384,4096), (1024,256), (64,16), then simple length-4 stage
__device__ void fft_fwd(float2* S, const float2* TW, int tid) {
    fwd_fused<16384>(S, TW, tid); __syncthreads();
    fwd_fused<1024>(S, TW, tid);  __syncthreads();
    fwd_fused<64>(S, TW, tid);    __syncthreads();
    #pragma unroll
    for (int k = 0; k < NBFLY / TPB; k++) {
        int b = tid + k * TPB;
        int i0 = 4 * b;
        float2 a0 = S[phys(i0)], a1 = S[phys(i0 + 1)], a2 = S[phys(i0 + 2)], a3 = S[phys(i0 + 3)];
        float2 t0 = cadd(a0, a2), t1 = csub(a0, a2);
        float2 t2 = cadd(a1, a3), t3 = csub(a1, a3);
        S[phys(i0)]     = cadd(t0, t2);
        S[phys(i0 + 1)] = make_float2(t1.x + t3.y, t1.y - t3.x);
        S[phys(i0 + 2)] = csub(t0, t2);
        S[phys(i0 + 3)] = make_float2(t1.x - t3.y, t1.y + t3.x);
    }
    __syncthreads();
}

// ---------------- fused inverse: two DIT radix-4 stages (l and 4l) per smem pass
template <int l>
__device__ __forceinline__ void inv_fused(float2* S, const float2* TW, int tid) {
    const int st    = l / 4;
    const int tmul  = NFFT / l;      // stage l
    const int tmul4 = tmul / 4;      // stage 4l
    #pragma unroll
    for (int ss = 0; ss < NSETS / TPB; ss++) {
        int s  = tid + ss * TPB;
        int j  = s & (st - 1);
        int i0 = (s / st) * (4 * l) + j;
        float2 x[16];
        #pragma unroll
        for (int m = 0; m < 16; m++) x[m] = S[phys(i0 + m * st)];
        // stage l (span st): groups {4r..4r+3}, shared twiddle base j
        {
            float2 w1 = conj2(twl(TW, j * tmul));
            float2 w2 = cmul(w1, w1), w3 = cmul(w2, w1);
            #pragma unroll
            for (int r = 0; r < 4; r++) {
                float2 a0 = x[4 * r], a1 = x[4 * r + 1], a2 = x[4 * r + 2], a3 = x[4 * r + 3];
                float2 d1 = cmul(a1, w1), d2 = cmul(a2, w2), d3 = cmul(a3, w3);
                float2 u0 = cadd(a0, d2), u1 = csub(a0, d2);
                float2 u2 = cadd(d1, d3), u3 = csub(d1, d3);
                x[4 * r]     = cadd(u0, u2);
                x[4 * r + 1] = make_float2(u1.x - u3.y, u1.y + u3.x);
                x[4 * r + 2] = csub(u0, u2);
                x[4 * r + 3] = make_float2(u1.x + u3.y, u1.y - u3.x);
            }
        }
        // stage 4l (span 4*st): groups {g, g+4, g+8, g+12}
        #pragma unroll
        for (int g = 0; g < 4; g++) {
            float2 w1 = conj2(twl(TW, (j + g * st) * tmul4));
            float2 w2 = cmul(w1, w1), w3 = cmul(w2, w1);
            float2 a0 = x[g], a1 = x[g + 4], a2 = x[g + 8], a3 = x[g + 12];
            float2 d1 = cmul(a1, w1), d2 = cmul(a2, w2), d3 = cmul(a3, w3);
            float2 u0 = cadd(a0, d2), u1 = csub(a0, d2);
            float2 u2 = cadd(d1, d3), u3 = csub(d1, d3);
            x[g]      = cadd(u0, u2);
            x[g + 4]  = make_float2(u1.x - u3.y, u1.y + u3.x);
            x[g + 8]  = csub(u0, u2);
            x[g + 12] = make_float2(u1.x + u3.y, u1.y - u3.x);
        }
        #pragma unroll
        for (int m = 0; m < 16; m++) S[phys(i0 + m * st)] = x[m];
    }
}

// inverse: simple length-4 stage, then fused (16,64), (256,1024), (4096,16384)
__device__ void fft_inv(float2* S, const float2* TW, int tid) {
    #pragma unroll
    for (int k = 0; k < NBFLY / TPB; k++) {
        int b = tid + k * TPB;
        int i0 = 4 * b;
        float2 a0 = S[phys(i0)], a1 = S[phys(i0 + 1)], a2 = S[phys(i0 + 2)], a3 = S[phys(i0 + 3)];
        float2 u0 = cadd(a0, a2), u1 = csub(a0, a2);
        float2 u2 = cadd(a1, a3), u3 = csub(a1, a3);
        S[phys(i0)]     = cadd(u0, u2);
        S[phys(i0 + 1)] = make_float2(u1.x - u3.y, u1.y + u3.x);
        S[phys(i0 + 2)] = csub(u0, u2);
        S[phys(i0 + 3)] = make_float2(u1.x + u3.y, u1.y - u3.x);
    }
    __syncthreads();
    inv_fused<16>(S, TW, tid);   __syncthreads();
    inv_fused<256>(S, TW, tid);  __syncthreads();
    inv_fused<4096>(S, TW, tid); __syncthreads();
}

// K0: filter spectrum per group. grid = G_, block = TPB
__global__ void __launch_bounds__(TPB, 1)
filter_fft_kernel(const float* __restrict__ h) {
    extern __shared__ float2 smem[];
    float2* S  = smem;
    float2* TW = smem + S_F2;
    const int tid = threadIdx.x;
    const int g = blockIdx.x;
    load_tw(TW, tid);
    const float* hr = h + (size_t)g * L_;
    for (int i = tid; i < L_; i += TPB)        S[phys(i)] = make_float2(hr[i], 0.0f);
    for (int i = L_ + tid; i < NFFT; i += TPB) S[phys(i)] = make_float2(0.0f, 0.0f);
    __syncthreads();
    fft_fwd(S, TW, tid);
    const float sc = 1.0f / (float)NFFT;   // fold IFFT scale into filter spectrum
    float2* out = g_HF + (size_t)g * NFFT;
    for (int k = tid; k < NFFT; k += TPB) {
        float2 v = S[phys(k)];
        out[k] = make_float2(v.x * sc, v.y * sc);
    }
}

// K1: kvP[b,cp,l] = (kv[2cp], kv[2cp+1]) with kv = x2*v.
// grid (D/32, L/32, B), block (32,8)
__global__ void kv_transpose_kernel(const float* __restrict__ x2,
                                    const float* __restrict__ v) {
    __shared__ float tile[32][33];           // [l_local][c_local]
    const int tx = threadIdx.x, ty = threadIdx.y;
    const int c0 = blockIdx.x * 32, l0 = blockIdx.y * 32, b = blockIdx.z;
    #pragma unroll
    for (int k = 0; k < 4; k++) {
        int l = l0 + ty + k * 8;
        size_t idx = ((size_t)(b * L_ + l)) * D_ + (c0 + tx);
        tile[ty + k * 8][tx] = x2[idx] * v[idx];
    }
    __syncthreads();
    const int cp0 = blockIdx.x * 16;
    #pragma unroll
    for (int k = 0; k < 2; k++) {
        int u = ty + k * 8;                  // channel-pair local index 0..15
        int l = l0 + tx;
        float2 pr = make_float2(tile[tx][2 * u], tile[tx][2 * u + 1]);
        g_kvP[((size_t)(b * CP_ + cp0 + u)) * L_ + l] = pr;
    }
}

// K2: per (b, channel-pair) packed FFT convolution + bias. grid = B*CP_, block = TPB
__global__ void __launch_bounds__(TPB, 1)
conv_fft_kernel(const float* __restrict__ conv_bias) {
    extern __shared__ float2 smem[];
    float2* S  = smem;
    float2* TW = smem + S_F2;
    const int tid = threadIdx.x;
    const int row = blockIdx.x;              // = b*CP_ + cp
    const int cp  = row & (CP_ - 1);
    const int c0  = cp * 2;
    const int g   = c0 >> 3;                 // both channels share the group
    load_tw(TW, tid);
    const float2* kv = g_kvP + (size_t)row * L_;
    for (int i = tid; i < L_; i += TPB)        S[phys(i)] = kv[i];
    for (int i = L_ + tid; i < NFFT; i += TPB) S[phys(i)] = make_float2(0.0f, 0.0f);
    __syncthreads();
    fft_fwd(S, TW, tid);
    const float2* HF = g_HF + (size_t)g * NFFT;
    for (int k = tid; k < NFFT; k += TPB) {
        S[phys(k)] = cmul(S[phys(k)], __ldg(&HF[k]));
    }
    __syncthreads();
    fft_inv(S, TW, tid);
    const float bias0 = conv_bias[c0];
    const float bias1 = conv_bias[c0 + 1];
    float2* out = g_yP + (size_t)row * L_;
    for (int i = tid; i < L_; i += TPB) {
        float2 s = S[phys(i)];
        float2 k2 = kv[i];
        out[i] = make_float2(s.x + k2.x * bias0, s.y + k2.y * bias1);
    }
}

// K3: out[b,l,c] = x1[b,l,c] * y[b,c,l]. grid (D/32, L/32, B), block (32,8)
__global__ void gate_transpose_kernel(const float* __restrict__ x1,
                                      float* __restrict__ out) {
    __shared__ float tile[32][33];           // [c_local][l_local]
    const int tx = threadIdx.x, ty = threadIdx.y;
    const int c0 = blockIdx.x * 32, l0 = blockIdx.y * 32, b = blockIdx.z;
    const int cp0 = blockIdx.x * 16;
    #pragma unroll
    for (int k = 0; k < 2; k++) {
        int u = ty + k * 8;                  // channel-pair local index
        int l = l0 + tx;
        float2 yv = g_yP[((size_t)(b * CP_ + cp0 + u)) * L_ + l];
        tile[2 * u][tx]     = yv.x;
        tile[2 * u + 1][tx] = yv.y;
    }
    __syncthreads();
    #pragma unroll
    for (int k = 0; k < 4; k++) {
        int l = l0 + ty + k * 8;
        size_t idx = ((size_t)(b * L_ + l)) * D_ + (c0 + tx);
        out[idx] = x1[idx] * tile[tx][ty + k * 8];
    }
}

extern "C" void kernel_launch(void* const* d_in, const int* in_sizes, int n_in,
                              void* d_out, int out_size) {
    const float* x1   = (const float*)d_in[0];
    const float* x2   = (const float*)d_in[1];
    const float* v    = (const float*)d_in[2];
    const float* h    = (const float*)d_in[3];
    const float* bias = (const float*)d_in[4];
    float* out = (float*)d_out;

    cudaFuncSetAttribute(filter_fft_kernel,
                         cudaFuncAttributeMaxDynamicSharedMemorySize, SMEM_BYTES);
    cudaFuncSetAttribute(conv_fft_kernel,
                         cudaFuncAttributeMaxDynamicSharedMemorySize, SMEM_BYTES);

    dim3 tgrid(D_ / 32, L_ / 32, B_);
    dim3 tblk(32, 8);

    twiddle_kernel<<<TWN / 256, 256>>>();
    filter_fft_kernel<<<G_, TPB, SMEM_BYTES>>>(h);
    kv_transpose_kernel<<<tgrid, tblk>>>(x2, v);
    conv_fft_kernel<<<B_ * CP_, TPB, SMEM_BYTES>>>(bias);
    gate_transpose_kernel<<<tgrid, tblk>>>(x1, out);
}

// round 12
// speedup vs baseline: 3.2854x; 1.1927x over previous
#include <cuda_runtime.h>
#include <cuda_bf16.h>
#include <cstdint>

// Shapes
#define B_  2
#define L_  8192
#define G_  256
#define DG_ 8
#define D_  2048          // G_*DG_
#define CP_ (D_/2)        // 1024 channel pairs
#define NFFT 16384        // 2*L_, 4^7
#define NBFLY (NFFT/4)    // 4096
#define NSETS (NFFT/16)   // 1024 fused radix-16 sets per pass
#define TPB 1024
#define TWN  (NFFT/4)     // quarter-circle twiddle table

// skewed smem index for the data array
__device__ __forceinline__ int phys(int i) { return i + (i >> 5); }

#define S_F2   (NFFT + NFFT/32)            // 16896
#define TW_F2  (TWN + TWN/32)              // 4224 (skewed twiddle storage)
#define SMEM_F2 (S_F2 + TW_F2)             // 21120
#define SMEM_BYTES (SMEM_F2 * (int)sizeof(float2))  // 168960 B

// scratch (device globals: allocation-free)
__device__ float2 g_kvP[(size_t)B_ * CP_ * L_];   // (B, CP, L) packed kv pairs
__device__ float2 g_yP [(size_t)B_ * CP_ * L_];   // (B, CP, L) packed conv outputs
__device__ float2 g_HF [(size_t)G_ * NFFT];       // per-group filter spectrum (scrambled, /N)
__device__ float2 g_TW [TWN];                     // twiddle master copy

__device__ __forceinline__ float2 cadd(float2 a, float2 b) { return make_float2(a.x + b.x, a.y + b.y); }
__device__ __forceinline__ float2 csub(float2 a, float2 b) { return make_float2(a.x - b.x, a.y - b.y); }
__device__ __forceinline__ float2 cmul(float2 a, float2 b) {
    return make_float2(a.x * b.x - a.y * b.y, a.x * b.y + a.y * b.x);
}
__device__ __forceinline__ float2 conj2(float2 a) { return make_float2(a.x, -a.y); }

// skewed twiddle read
__device__ __forceinline__ float2 twl(const float2* TW, int k) { return TW[k + (k >> 5)]; }

// K-1: build twiddle table once. TW[k] = e^{-2*pi*i*k/NFFT}
__global__ void twiddle_kernel() {
    int k = blockIdx.x * blockDim.x + threadIdx.x;
    if (k < TWN) {
        float s, c;
        sincospif(-(float)k * (1.0f / (NFFT / 2)), &s, &c);
        g_TW[k] = make_float2(c, s);
    }
}

__device__ __forceinline__ void load_tw(float2* TW, int tid) {
    for (int k = tid; k < TWN; k += TPB) TW[k + (k >> 5)] = g_TW[k];
}

// ---------------- fused forward: two DIF radix-4 stages (Lc and Lc/4) per smem pass
template <int Lc>
__device__ __forceinline__ void fwd_fused(float2* S, const float2* TW, int tid) {
    const int st   = Lc / 16;
    const int tmul = NFFT / Lc;
    #pragma unroll
    for (int ss = 0; ss < NSETS / TPB; ss++) {
        int s  = tid + ss * TPB;
        int j  = s & (st - 1);
        int i0 = (s / st) * Lc + j;
        float2 x[16];
        #pragma unroll
        for (int m = 0; m < 16; m++) x[m] = S[phys(i0 + m * st)];
        // stage length Lc (span 4*st): groups {g, g+4, g+8, g+12}
        #pragma unroll
        for (int g = 0; g < 4; g++) {
            float2 a0 = x[g], a1 = x[g + 4], a2 = x[g + 8], a3 = x[g + 12];
            float2 t0 = cadd(a0, a2), t1 = csub(a0, a2);
            float2 t2 = cadd(a1, a3), t3 = csub(a1, a3);
            float2 w1 = twl(TW, (j + g * st) * tmul);
            float2 w2 = cmul(w1, w1), w3 = cmul(w2, w1);
            x[g]      = cadd(t0, t2);
            x[g + 4]  = cmul(make_float2(t1.x + t3.y, t1.y - t3.x), w1);
            x[g + 8]  = cmul(csub(t0, t2), w2);
            x[g + 12] = cmul(make_float2(t1.x - t3.y, t1.y + t3.x), w3);
        }
        // stage length Lc/4 (span st): groups {4r..4r+3}, shared twiddle base j
        {
            float2 w1 = twl(TW, j * tmul * 4);
            float2 w2 = cmul(w1, w1), w3 = cmul(w2, w1);
            #pragma unroll
            for (int r = 0; r < 4; r++) {
                float2 a0 = x[4 * r], a1 = x[4 * r + 1], a2 = x[4 * r + 2], a3 = x[4 * r + 3];
                float2 t0 = cadd(a0, a2), t1 = csub(a0, a2);
                float2 t2 = cadd(a1, a3), t3 = csub(a1, a3);
                x[4 * r]     = cadd(t0, t2);
                x[4 * r + 1] = cmul(make_float2(t1.x + t3.y, t1.y - t3.x), w1);
                x[4 * r + 2] = cmul(csub(t0, t2), w2);
                x[4 * r + 3] = cmul(make_float2(t1.x - t3.y, t1.y + t3.x), w3);
            }
        }
        #pragma unroll
        for (int m = 0; m < 16; m++) S[phys(i0 + m * st)] = x[m];
    }
}

// forward without the final length-4 stage: fused (16384,4096), (1024,256), (64,16)
__device__ void fft_fwd_noLast(float2* S, const float2* TW, int tid) {
    fwd_fused<16384>(S, TW, tid); __syncthreads();
    fwd_fused<1024>(S, TW, tid);  __syncthreads();
    fwd_fused<64>(S, TW, tid);    __syncthreads();
}

// ---------------- fused inverse: two DIT radix-4 stages (l and 4l) per smem pass
template <int l>
__device__ __forceinline__ void inv_fused(float2* S, const float2* TW, int tid) {
    const int st    = l / 4;
    const int tmul  = NFFT / l;      // stage l
    const int tmul4 = tmul / 4;      // stage 4l
    #pragma unroll
    for (int ss = 0; ss < NSETS / TPB; ss++) {
        int s  = tid + ss * TPB;
        int j  = s & (st - 1);
        int i0 = (s / st) * (4 * l) + j;
        float2 x[16];
        #pragma unroll
        for (int m = 0; m < 16; m++) x[m] = S[phys(i0 + m * st)];
        // stage l (span st): groups {4r..4r+3}, shared twiddle base j
        {
            float2 w1 = conj2(twl(TW, j * tmul));
            float2 w2 = cmul(w1, w1), w3 = cmul(w2, w1);
            #pragma unroll
            for (int r = 0; r < 4; r++) {
                float2 a0 = x[4 * r], a1 = x[4 * r + 1], a2 = x[4 * r + 2], a3 = x[4 * r + 3];
                float2 d1 = cmul(a1, w1), d2 = cmul(a2, w2), d3 = cmul(a3, w3);
                float2 u0 = cadd(a0, d2), u1 = csub(a0, d2);
                float2 u2 = cadd(d1, d3), u3 = csub(d1, d3);
                x[4 * r]     = cadd(u0, u2);
                x[4 * r + 1] = make_float2(u1.x - u3.y, u1.y + u3.x);
                x[4 * r + 2] = csub(u0, u2);
                x[4 * r + 3] = make_float2(u1.x + u3.y, u1.y - u3.x);
            }
        }
        // stage 4l (span 4*st): groups {g, g+4, g+8, g+12}
        #pragma unroll
        for (int g = 0; g < 4; g++) {
            float2 w1 = conj2(twl(TW, (j + g * st) * tmul4));
            float2 w2 = cmul(w1, w1), w3 = cmul(w2, w1);
            float2 a0 = x[g], a1 = x[g + 4], a2 = x[g + 8], a3 = x[g + 12];
            float2 d1 = cmul(a1, w1), d2 = cmul(a2, w2), d3 = cmul(a3, w3);
            float2 u0 = cadd(a0, d2), u1 = csub(a0, d2);
            float2 u2 = cadd(d1, d3), u3 = csub(d1, d3);
            x[g]      = cadd(u0, u2);
            x[g + 4]  = make_float2(u1.x - u3.y, u1.y + u3.x);
            x[g + 8]  = csub(u0, u2);
            x[g + 12] = make_float2(u1.x + u3.y, u1.y - u3.x);
        }
        #pragma unroll
        for (int m = 0; m < 16; m++) S[phys(i0 + m * st)] = x[m];
    }
}

// inverse tail: fused (16,64), (256,1024), (4096,16384). Assumes the length-4
// stage was already applied (inside the fused middle pass of the conv kernel).
__device__ void fft_inv_tail(float2* S, const float2* TW, int tid) {
    inv_fused<16>(S, TW, tid);   __syncthreads();
    inv_fused<256>(S, TW, tid);  __syncthreads();
    inv_fused<4096>(S, TW, tid); __syncthreads();
}

// K0: filter spectrum per group. grid = G_, block = TPB
__global__ void __launch_bounds__(TPB, 1)
filter_fft_kernel(const float* __restrict__ h) {
    extern __shared__ float2 smem[];
    float2* S  = smem;
    float2* TW = smem + S_F2;
    const int tid = threadIdx.x;
    const int g = blockIdx.x;
    load_tw(TW, tid);
    const float* hr = h + (size_t)g * L_;
    for (int i = tid; i < L_; i += TPB)        S[phys(i)] = make_float2(hr[i], 0.0f);
    for (int i = L_ + tid; i < NFFT; i += TPB) S[phys(i)] = make_float2(0.0f, 0.0f);
    __syncthreads();
    fft_fwd_noLast(S, TW, tid);
    // final length-4 DIF stage fused with the scaled writeout
    const float sc = 1.0f / (float)NFFT;   // fold IFFT scale into filter spectrum
    float2* out = g_HF + (size_t)g * NFFT;
    #pragma unroll
    for (int k = 0; k < NBFLY / TPB; k++) {
        int b = tid + k * TPB;
        int i0 = 4 * b;
        float2 a0 = S[phys(i0)], a1 = S[phys(i0 + 1)], a2 = S[phys(i0 + 2)], a3 = S[phys(i0 + 3)];
        float2 t0 = cadd(a0, a2), t1 = csub(a0, a2);
        float2 t2 = cadd(a1, a3), t3 = csub(a1, a3);
        float2 y0 = cadd(t0, t2);
        float2 y1 = make_float2(t1.x + t3.y, t1.y - t3.x);
        float2 y2 = csub(t0, t2);
        float2 y3 = make_float2(t1.x - t3.y, t1.y + t3.x);
        out[i0]     = make_float2(y0.x * sc, y0.y * sc);
        out[i0 + 1] = make_float2(y1.x * sc, y1.y * sc);
        out[i0 + 2] = make_float2(y2.x * sc, y2.y * sc);
        out[i0 + 3] = make_float2(y3.x * sc, y3.y * sc);
    }
}

// K1: kvP[b,cp,l] = (kv[2cp], kv[2cp+1]) with kv = x2*v.
// grid (D/32, L/32, B), block (32,8)
__global__ void kv_transpose_kernel(const float* __restrict__ x2,
                                    const float* __restrict__ v) {
    __shared__ float tile[32][33];           // [l_local][c_local]
    const int tx = threadIdx.x, ty = threadIdx.y;
    const int c0 = blockIdx.x * 32, l0 = blockIdx.y * 32, b = blockIdx.z;
    #pragma unroll
    for (int k = 0; k < 4; k++) {
        int l = l0 + ty + k * 8;
        size_t idx = ((size_t)(b * L_ + l)) * D_ + (c0 + tx);
        tile[ty + k * 8][tx] = x2[idx] * v[idx];
    }
    __syncthreads();
    const int cp0 = blockIdx.x * 16;
    #pragma unroll
    for (int k = 0; k < 2; k++) {
        int u = ty + k * 8;                  // channel-pair local index 0..15
        int l = l0 + tx;
        float2 pr = make_float2(tile[tx][2 * u], tile[tx][2 * u + 1]);
        g_kvP[((size_t)(b * CP_ + cp0 + u)) * L_ + l] = pr;
    }
}

// K2: per (b, channel-pair) packed FFT convolution + bias. grid = B*CP_, block = TPB
__global__ void __launch_bounds__(TPB, 1)
conv_fft_kernel(const float* __restrict__ conv_bias) {
    extern __shared__ float2 smem[];
    float2* S  = smem;
    float2* TW = smem + S_F2;
    const int tid = threadIdx.x;
    const int row = blockIdx.x;              // = b*CP_ + cp
    const int cp  = row & (CP_ - 1);
    const int c0  = cp * 2;
    const int g   = c0 >> 3;                 // both channels share the group
    load_tw(TW, tid);
    const float2* kv = g_kvP + (size_t)row * L_;
    for (int i = tid; i < L_; i += TPB)        S[phys(i)] = kv[i];
    for (int i = L_ + tid; i < NFFT; i += TPB) S[phys(i)] = make_float2(0.0f, 0.0f);
    __syncthreads();
    fft_fwd_noLast(S, TW, tid);
    // fused middle: final fwd length-4 stage + pointwise *HF + first inv length-4 stage
    const float2* HF = g_HF + (size_t)g * NFFT;
    #pragma unroll
    for (int k = 0; k < NBFLY / TPB; k++) {
        int b = tid + k * TPB;
        int i0 = 4 * b;
        float2 a0 = S[phys(i0)], a1 = S[phys(i0 + 1)], a2 = S[phys(i0 + 2)], a3 = S[phys(i0 + 3)];
        // forward length-4 butterfly
        float2 t0 = cadd(a0, a2), t1 = csub(a0, a2);
        float2 t2 = cadd(a1, a3), t3 = csub(a1, a3);
        float2 y0 = cadd(t0, t2);
        float2 y1 = make_float2(t1.x + t3.y, t1.y - t3.x);
        float2 y2 = csub(t0, t2);
        float2 y3 = make_float2(t1.x - t3.y, t1.y + t3.x);
        // pointwise multiply by filter spectrum (same scrambled order)
        y0 = cmul(y0, __ldg(&HF[i0]));
        y1 = cmul(y1, __ldg(&HF[i0 + 1]));
        y2 = cmul(y2, __ldg(&HF[i0 + 2]));
        y3 = cmul(y3, __ldg(&HF[i0 + 3]));
        // inverse length-4 butterfly
        float2 u0 = cadd(y0, y2), u1 = csub(y0, y2);
        float2 u2 = cadd(y1, y3), u3 = csub(y1, y3);
        S[phys(i0)]     = cadd(u0, u2);
        S[phys(i0 + 1)] = make_float2(u1.x - u3.y, u1.y + u3.x);
        S[phys(i0 + 2)] = csub(u0, u2);
        S[phys(i0 + 3)] = make_float2(u1.x + u3.y, u1.y - u3.x);
    }
    __syncthreads();
    fft_inv_tail(S, TW, tid);
    const float bias0 = conv_bias[c0];
    const float bias1 = conv_bias[c0 + 1];
    float2* out = g_yP + (size_t)row * L_;
    for (int i = tid; i < L_; i += TPB) {
        float2 s = S[phys(i)];
        float2 k2 = kv[i];
        out[i] = make_float2(s.x + k2.x * bias0, s.y + k2.y * bias1);
    }
}

// K3: out[b,l,c] = x1[b,l,c] * y[b,c,l]. grid (D/32, L/32, B), block (32,8)
__global__ void gate_transpose_kernel(const float* __restrict__ x1,
                                      float* __restrict__ out) {
    __shared__ float tile[32][33];           // [c_local][l_local]
    const int tx = threadIdx.x, ty = threadIdx.y;
    const int c0 = blockIdx.x * 32, l0 = blockIdx.y * 32, b = blockIdx.z;
    const int cp0 = blockIdx.x * 16;
    #pragma unroll
    for (int k = 0; k < 2; k++) {
        int u = ty + k * 8;                  // channel-pair local index
        int l = l0 + tx;
        float2 yv = g_yP[((size_t)(b * CP_ + cp0 + u)) * L_ + l];
        tile[2 * u][tx]     = yv.x;
        tile[2 * u + 1][tx] = yv.y;
    }
    __syncthreads();
    #pragma unroll
    for (int k = 0; k < 4; k++) {
        int l = l0 + ty + k * 8;
        size_t idx = ((size_t)(b * L_ + l)) * D_ + (c0 + tx);
        out[idx] = x1[idx] * tile[tx][ty + k * 8];
    }
}

extern "C" void kernel_launch(void* const* d_in, const int* in_sizes, int n_in,
                              void* d_out, int out_size) {
    const float* x1   = (const float*)d_in[0];
    const float* x2   = (const float*)d_in[1];
    const float* v    = (const float*)d_in[2];
    const float* h    = (const float*)d_in[3];
    const float* bias = (const float*)d_in[4];
    float* out = (float*)d_out;

    cudaFuncSetAttribute(filter_fft_kernel,
                         cudaFuncAttributeMaxDynamicSharedMemorySize, SMEM_BYTES);
    cudaFuncSetAttribute(conv_fft_kernel,
                         cudaFuncAttributeMaxDynamicSharedMemorySize, SMEM_BYTES);

    dim3 tgrid(D_ / 32, L_ / 32, B_);
    dim3 tblk(32, 8);

    twiddle_kernel<<<TWN / 256, 256>>>();
    filter_fft_kernel<<<G_, TPB, SMEM_BYTES>>>(h);
    kv_transpose_kernel<<<tgrid, tblk>>>(x2, v);
    conv_fft_kernel<<<B_ * CP_, TPB, SMEM_BYTES>>>(bias);
    gate_transpose_kernel<<<tgrid, tblk>>>(x1, out);
}

// round 13
// speedup vs baseline: 4.0238x; 1.2247x over previous
#include <cuda_runtime.h>
#include <cuda_bf16.h>
#include <cstdint>

// Shapes
#define B_  2
#define L_  8192
#define G_  256
#define DG_ 8
#define D_  2048          // G_*DG_
#define CP_ (D_/2)        // 1024 channel pairs
#define NFFT 16384        // 2*L_, 4^7
#define NBFLY (NFFT/4)    // 4096
#define NSETS (NFFT/16)   // 1024 fused radix-16 sets per pass
#define TPB 1024
#define TWN  (NFFT/4)     // quarter-circle twiddle table

// skewed smem index for the data array
__device__ __forceinline__ int phys(int i) { return i + (i >> 5); }

#define S_F2   (NFFT + NFFT/32)            // 16896
#define TW_F2  (TWN + TWN/32)              // 4224 (skewed twiddle storage)
#define SMEM_F2 (S_F2 + TW_F2)             // 21120
#define SMEM_BYTES (SMEM_F2 * (int)sizeof(float2))  // 168960 B

// scratch (device globals: allocation-free)
__device__ float2 g_kvP[(size_t)B_ * CP_ * L_];   // (B, CP, L) packed kv pairs
__device__ float2 g_yP [(size_t)B_ * CP_ * L_];   // (B, CP, L) packed conv outputs
__device__ float2 g_HF [(size_t)G_ * NFFT];       // per-group filter spectrum (scrambled, /N)
__device__ float2 g_TW [TWN];                     // twiddle master copy

__device__ __forceinline__ float2 cadd(float2 a, float2 b) { return make_float2(a.x + b.x, a.y + b.y); }
__device__ __forceinline__ float2 csub(float2 a, float2 b) { return make_float2(a.x - b.x, a.y - b.y); }
__device__ __forceinline__ float2 cmul(float2 a, float2 b) {
    return make_float2(a.x * b.x - a.y * b.y, a.x * b.y + a.y * b.x);
}
__device__ __forceinline__ float2 conj2(float2 a) { return make_float2(a.x, -a.y); }

// skewed twiddle read
__device__ __forceinline__ float2 twl(const float2* TW, int k) { return TW[k + (k >> 5)]; }

// K-1: build twiddle table once. TW[k] = e^{-2*pi*i*k/NFFT}
__global__ void twiddle_kernel() {
    int k = blockIdx.x * blockDim.x + threadIdx.x;
    if (k < TWN) {
        float s, c;
        sincospif(-(float)k * (1.0f / (NFFT / 2)), &s, &c);
        g_TW[k] = make_float2(c, s);
    }
}

__device__ __forceinline__ void load_tw(float2* TW, int tid) {
    for (int k = tid; k < TWN; k += TPB) TW[k + (k >> 5)] = g_TW[k];
}

// ---------------- fused forward: two DIF radix-4 stages (Lc and Lc/4) per smem pass
template <int Lc>
__device__ __forceinline__ void fwd_fused(float2* S, const float2* TW, int tid) {
    const int st   = Lc / 16;
    const int tmul = NFFT / Lc;
    #pragma unroll
    for (int ss = 0; ss < NSETS / TPB; ss++) {
        int s  = tid + ss * TPB;
        int j  = s & (st - 1);
        int i0 = (s / st) * Lc + j;
        float2 x[16];
        #pragma unroll
        for (int m = 0; m < 16; m++) x[m] = S[phys(i0 + m * st)];
        // stage length Lc (span 4*st)
        #pragma unroll
        for (int g = 0; g < 4; g++) {
            float2 a0 = x[g], a1 = x[g + 4], a2 = x[g + 8], a3 = x[g + 12];
            float2 t0 = cadd(a0, a2), t1 = csub(a0, a2);
            float2 t2 = cadd(a1, a3), t3 = csub(a1, a3);
            float2 w1 = twl(TW, (j + g * st) * tmul);
            float2 w2 = cmul(w1, w1), w3 = cmul(w2, w1);
            x[g]      = cadd(t0, t2);
            x[g + 4]  = cmul(make_float2(t1.x + t3.y, t1.y - t3.x), w1);
            x[g + 8]  = cmul(csub(t0, t2), w2);
            x[g + 12] = cmul(make_float2(t1.x - t3.y, t1.y + t3.x), w3);
        }
        // stage length Lc/4 (span st)
        {
            float2 w1 = twl(TW, j * tmul * 4);
            float2 w2 = cmul(w1, w1), w3 = cmul(w2, w1);
            #pragma unroll
            for (int r = 0; r < 4; r++) {
                float2 a0 = x[4 * r], a1 = x[4 * r + 1], a2 = x[4 * r + 2], a3 = x[4 * r + 3];
                float2 t0 = cadd(a0, a2), t1 = csub(a0, a2);
                float2 t2 = cadd(a1, a3), t3 = csub(a1, a3);
                x[4 * r]     = cadd(t0, t2);
                x[4 * r + 1] = cmul(make_float2(t1.x + t3.y, t1.y - t3.x), w1);
                x[4 * r + 2] = cmul(csub(t0, t2), w2);
                x[4 * r + 3] = cmul(make_float2(t1.x - t3.y, t1.y + t3.x), w3);
            }
        }
        #pragma unroll
        for (int m = 0; m < 16; m++) S[phys(i0 + m * st)] = x[m];
    }
}

// first forward pass (stages 16384, 4096) reading x[m] directly from global.
// Input has only NFFT/2 nonzero elements (m<8); upper half implicitly zero.
// Layout: thread tid owns elements { tid + m*1024 }, coalesced per m.
__device__ __forceinline__ void fwd_first_from_global(float2* S, const float2* TW,
                                                      int tid, const float2* __restrict__ in) {
    const int j = tid;                       // st=1024, tmul=1, one set per thread
    float2 x[16];
    #pragma unroll
    for (int m = 0; m < 8; m++) x[m] = __ldg(&in[j + m * 1024]);
    // stage 16384 with a2=a3=0: t0=t1=a0, t2=t3=a1
    #pragma unroll
    for (int g = 0; g < 4; g++) {
        float2 a0 = x[g], a1 = x[g + 4];
        float2 w1 = twl(TW, j + g * 1024);
        float2 w2 = cmul(w1, w1), w3 = cmul(w2, w1);
        x[g]      = cadd(a0, a1);
        x[g + 4]  = cmul(make_float2(a0.x + a1.y, a0.y - a1.x), w1);   // a0 - i a1
        x[g + 8]  = cmul(csub(a0, a1), w2);
        x[g + 12] = cmul(make_float2(a0.x - a1.y, a0.y + a1.x), w3);   // a0 + i a1
    }
    // stage 4096 (span 1024), twiddle base j*4
    {
        float2 w1 = twl(TW, j * 4);
        float2 w2 = cmul(w1, w1), w3 = cmul(w2, w1);
        #pragma unroll
        for (int r = 0; r < 4; r++) {
            float2 a0 = x[4 * r], a1 = x[4 * r + 1], a2 = x[4 * r + 2], a3 = x[4 * r + 3];
            float2 t0 = cadd(a0, a2), t1 = csub(a0, a2);
            float2 t2 = cadd(a1, a3), t3 = csub(a1, a3);
            x[4 * r]     = cadd(t0, t2);
            x[4 * r + 1] = cmul(make_float2(t1.x + t3.y, t1.y - t3.x), w1);
            x[4 * r + 2] = cmul(csub(t0, t2), w2);
            x[4 * r + 3] = cmul(make_float2(t1.x - t3.y, t1.y + t3.x), w3);
        }
    }
    #pragma unroll
    for (int m = 0; m < 16; m++) S[phys(j + m * 1024)] = x[m];
}

// same, for a real-valued global input (filter h)
__device__ __forceinline__ void fwd_first_from_global_real(float2* S, const float2* TW,
                                                           int tid, const float* __restrict__ in) {
    const int j = tid;
    float2 x[16];
    #pragma unroll
    for (int m = 0; m < 8; m++) x[m] = make_float2(__ldg(&in[j + m * 1024]), 0.0f);
    #pragma unroll
    for (int g = 0; g < 4; g++) {
        float2 a0 = x[g], a1 = x[g + 4];
        float2 w1 = twl(TW, j + g * 1024);
        float2 w2 = cmul(w1, w1), w3 = cmul(w2, w1);
        x[g]      = cadd(a0, a1);
        x[g + 4]  = cmul(make_float2(a0.x + a1.y, a0.y - a1.x), w1);
        x[g + 8]  = cmul(csub(a0, a1), w2);
        x[g + 12] = cmul(make_float2(a0.x - a1.y, a0.y + a1.x), w3);
    }
    {
        float2 w1 = twl(TW, j * 4);
        float2 w2 = cmul(w1, w1), w3 = cmul(w2, w1);
        #pragma unroll
        for (int r = 0; r < 4; r++) {
            float2 a0 = x[4 * r], a1 = x[4 * r + 1], a2 = x[4 * r + 2], a3 = x[4 * r + 3];
            float2 t0 = cadd(a0, a2), t1 = csub(a0, a2);
            float2 t2 = cadd(a1, a3), t3 = csub(a1, a3);
            x[4 * r]     = cadd(t0, t2);
            x[4 * r + 1] = cmul(make_float2(t1.x + t3.y, t1.y - t3.x), w1);
            x[4 * r + 2] = cmul(csub(t0, t2), w2);
            x[4 * r + 3] = cmul(make_float2(t1.x - t3.y, t1.y + t3.x), w3);
        }
    }
    #pragma unroll
    for (int m = 0; m < 16; m++) S[phys(j + m * 1024)] = x[m];
}

// ---------------- fused inverse: two DIT radix-4 stages (l and 4l) per smem pass
template <int l>
__device__ __forceinline__ void inv_fused(float2* S, const float2* TW, int tid) {
    const int st    = l / 4;
    const int tmul  = NFFT / l;
    const int tmul4 = tmul / 4;
    #pragma unroll
    for (int ss = 0; ss < NSETS / TPB; ss++) {
        int s  = tid + ss * TPB;
        int j  = s & (st - 1);
        int i0 = (s / st) * (4 * l) + j;
        float2 x[16];
        #pragma unroll
        for (int m = 0; m < 16; m++) x[m] = S[phys(i0 + m * st)];
        // stage l (span st)
        {
            float2 w1 = conj2(twl(TW, j * tmul));
            float2 w2 = cmul(w1, w1), w3 = cmul(w2, w1);
            #pragma unroll
            for (int r = 0; r < 4; r++) {
                float2 a0 = x[4 * r], a1 = x[4 * r + 1], a2 = x[4 * r + 2], a3 = x[4 * r + 3];
                float2 d1 = cmul(a1, w1), d2 = cmul(a2, w2), d3 = cmul(a3, w3);
                float2 u0 = cadd(a0, d2), u1 = csub(a0, d2);
                float2 u2 = cadd(d1, d3), u3 = csub(d1, d3);
                x[4 * r]     = cadd(u0, u2);
                x[4 * r + 1] = make_float2(u1.x - u3.y, u1.y + u3.x);
                x[4 * r + 2] = csub(u0, u2);
                x[4 * r + 3] = make_float2(u1.x + u3.y, u1.y - u3.x);
            }
        }
        // stage 4l (span 4*st)
        #pragma unroll
        for (int g = 0; g < 4; g++) {
            float2 w1 = conj2(twl(TW, (j + g * st) * tmul4));
            float2 w2 = cmul(w1, w1), w3 = cmul(w2, w1);
            float2 a0 = x[g], a1 = x[g + 4], a2 = x[g + 8], a3 = x[g + 12];
            float2 d1 = cmul(a1, w1), d2 = cmul(a2, w2), d3 = cmul(a3, w3);
            float2 u0 = cadd(a0, d2), u1 = csub(a0, d2);
            float2 u2 = cadd(d1, d3), u3 = csub(d1, d3);
            x[g]      = cadd(u0, u2);
            x[g + 4]  = make_float2(u1.x - u3.y, u1.y + u3.x);
            x[g + 8]  = csub(u0, u2);
            x[g + 12] = make_float2(u1.x + u3.y, u1.y - u3.x);
        }
        #pragma unroll
        for (int m = 0; m < 16; m++) S[phys(i0 + m * st)] = x[m];
    }
}

// last inverse pass (stages 4096, 16384) writing results + bias directly to
// global. Only elements i < L_ (m < 8) are kept.
__device__ __forceinline__ void inv_last_to_global(const float2* S, const float2* TW, int tid,
                                                   const float2* __restrict__ kv,
                                                   float2* __restrict__ out,
                                                   float bias0, float bias1) {
    const int j = tid;                   // st=1024, tmul=4, tmul4=1
    float2 x[16];
    #pragma unroll
    for (int m = 0; m < 16; m++) x[m] = S[phys(j + m * 1024)];
    // stage 4096 (span 1024): quartets of consecutive m, twiddle base j*4
    {
        float2 w1 = conj2(twl(TW, j * 4));
        float2 w2 = cmul(w1, w1), w3 = cmul(w2, w1);
        #pragma unroll
        for (int r = 0; r < 4; r++) {
            float2 a0 = x[4 * r], a1 = x[4 * r + 1], a2 = x[4 * r + 2], a3 = x[4 * r + 3];
            float2 d1 = cmul(a1, w1), d2 = cmul(a2, w2), d3 = cmul(a3, w3);
            float2 u0 = cadd(a0, d2), u1 = csub(a0, d2);
            float2 u2 = cadd(d1, d3), u3 = csub(d1, d3);
            x[4 * r]     = cadd(u0, u2);
            x[4 * r + 1] = make_float2(u1.x - u3.y, u1.y + u3.x);
            x[4 * r + 2] = csub(u0, u2);
            x[4 * r + 3] = make_float2(u1.x + u3.y, u1.y - u3.x);
        }
    }
    // stage 16384 (span 4096): only outputs m=g and m=g+4 are kept (i < L_)
    float2 y[8];
    #pragma unroll
    for (int g = 0; g < 4; g++) {
        float2 w1 = conj2(twl(TW, j + g * 1024));
        float2 w2 = cmul(w1, w1), w3 = cmul(w2, w1);
        float2 a0 = x[g], a1 = x[g + 4], a2 = x[g + 8], a3 = x[g + 12];
        float2 d1 = cmul(a1, w1), d2 = cmul(a2, w2), d3 = cmul(a3, w3);
        float2 u0 = cadd(a0, d2), u1 = csub(a0, d2);
        float2 u2 = cadd(d1, d3), u3 = csub(d1, d3);
        y[g]     = cadd(u0, u2);                                  // m = g
        y[g + 4] = make_float2(u1.x - u3.y, u1.y + u3.x);         // m = g+4
    }
    #pragma unroll
    for (int m = 0; m < 8; m++) {
        int i = j + m * 1024;
        float2 k2 = __ldg(&kv[i]);
        out[i] = make_float2(y[m].x + k2.x * bias0, y[m].y + k2.y * bias1);
    }
}

// K0: filter spectrum per group. grid = G_, block = TPB
__global__ void __launch_bounds__(TPB, 1)
filter_fft_kernel(const float* __restrict__ h) {
    extern __shared__ float2 smem[];
    float2* S  = smem;
    float2* TW = smem + S_F2;
    const int tid = threadIdx.x;
    const int g = blockIdx.x;
    load_tw(TW, tid);
    __syncthreads();
    fwd_first_from_global_real(S, TW, tid, h + (size_t)g * L_);
    __syncthreads();
    fwd_fused<1024>(S, TW, tid); __syncthreads();
    fwd_fused<64>(S, TW, tid);   __syncthreads();
    // final length-4 DIF stage fused with the scaled writeout
    const float sc = 1.0f / (float)NFFT;
    float2* out = g_HF + (size_t)g * NFFT;
    #pragma unroll
    for (int k = 0; k < NBFLY / TPB; k++) {
        int b = tid + k * TPB;
        int i0 = 4 * b;
        float2 a0 = S[phys(i0)], a1 = S[phys(i0 + 1)], a2 = S[phys(i0 + 2)], a3 = S[phys(i0 + 3)];
        float2 t0 = cadd(a0, a2), t1 = csub(a0, a2);
        float2 t2 = cadd(a1, a3), t3 = csub(a1, a3);
        float2 y0 = cadd(t0, t2);
        float2 y1 = make_float2(t1.x + t3.y, t1.y - t3.x);
        float2 y2 = csub(t0, t2);
        float2 y3 = make_float2(t1.x - t3.y, t1.y + t3.x);
        out[i0]     = make_float2(y0.x * sc, y0.y * sc);
        out[i0 + 1] = make_float2(y1.x * sc, y1.y * sc);
        out[i0 + 2] = make_float2(y2.x * sc, y2.y * sc);
        out[i0 + 3] = make_float2(y3.x * sc, y3.y * sc);
    }
}

// K1: kvP[b,cp,l] = (kv[2cp], kv[2cp+1]) with kv = x2*v.
// grid (D/32, L/32, B), block (32,8)
__global__ void kv_transpose_kernel(const float* __restrict__ x2,
                                    const float* __restrict__ v) {
    __shared__ float tile[32][33];           // [l_local][c_local]
    const int tx = threadIdx.x, ty = threadIdx.y;
    const int c0 = blockIdx.x * 32, l0 = blockIdx.y * 32, b = blockIdx.z;
    #pragma unroll
    for (int k = 0; k < 4; k++) {
        int l = l0 + ty + k * 8;
        size_t idx = ((size_t)(b * L_ + l)) * D_ + (c0 + tx);
        tile[ty + k * 8][tx] = x2[idx] * v[idx];
    }
    __syncthreads();
    const int cp0 = blockIdx.x * 16;
    #pragma unroll
    for (int k = 0; k < 2; k++) {
        int u = ty + k * 8;                  // channel-pair local index 0..15
        int l = l0 + tx;
        float2 pr = make_float2(tile[tx][2 * u], tile[tx][2 * u + 1]);
        g_kvP[((size_t)(b * CP_ + cp0 + u)) * L_ + l] = pr;
    }
}

// K2: per (b, channel-pair) packed FFT convolution + bias. grid = B*CP_, block = TPB
__global__ void __launch_bounds__(TPB, 1)
conv_fft_kernel(const float* __restrict__ conv_bias) {
    extern __shared__ float2 smem[];
    float2* S  = smem;
    float2* TW = smem + S_F2;
    const int tid = threadIdx.x;
    const int row = blockIdx.x;              // = b*CP_ + cp
    const int cp  = row & (CP_ - 1);
    const int c0  = cp * 2;
    const int g   = c0 >> 3;                 // both channels share the group
    load_tw(TW, tid);
    __syncthreads();
    const float2* kv = g_kvP + (size_t)row * L_;
    fwd_first_from_global(S, TW, tid, kv);
    __syncthreads();
    fwd_fused<1024>(S, TW, tid); __syncthreads();
    fwd_fused<64>(S, TW, tid);   __syncthreads();
    // fused middle: final fwd length-4 stage + pointwise *HF + first inv length-4 stage
    const float2* HF = g_HF + (size_t)g * NFFT;
    #pragma unroll
    for (int k = 0; k < NBFLY / TPB; k++) {
        int b = tid + k * TPB;
        int i0 = 4 * b;
        float2 a0 = S[phys(i0)], a1 = S[phys(i0 + 1)], a2 = S[phys(i0 + 2)], a3 = S[phys(i0 + 3)];
        float2 t0 = cadd(a0, a2), t1 = csub(a0, a2);
        float2 t2 = cadd(a1, a3), t3 = csub(a1, a3);
        float2 y0 = cadd(t0, t2);
        float2 y1 = make_float2(t1.x + t3.y, t1.y - t3.x);
        float2 y2 = csub(t0, t2);
        float2 y3 = make_float2(t1.x - t3.y, t1.y + t3.x);
        y0 = cmul(y0, __ldg(&HF[i0]));
        y1 = cmul(y1, __ldg(&HF[i0 + 1]));
        y2 = cmul(y2, __ldg(&HF[i0 + 2]));
        y3 = cmul(y3, __ldg(&HF[i0 + 3]));
        float2 u0 = cadd(y0, y2), u1 = csub(y0, y2);
        float2 u2 = cadd(y1, y3), u3 = csub(y1, y3);
        S[phys(i0)]     = cadd(u0, u2);
        S[phys(i0 + 1)] = make_float2(u1.x - u3.y, u1.y + u3.x);
        S[phys(i0 + 2)] = csub(u0, u2);
        S[phys(i0 + 3)] = make_float2(u1.x + u3.y, u1.y - u3.x);
    }
    __syncthreads();
    inv_fused<16>(S, TW, tid);  __syncthreads();
    inv_fused<256>(S, TW, tid); __syncthreads();
    inv_last_to_global(S, TW, tid, kv, g_yP + (size_t)row * L_,
                       conv_bias[c0], conv_bias[c0 + 1]);
}

// K3: out[b,l,c] = x1[b,l,c] * y[b,c,l]. grid (D/32, L/32, B), block (32,8)
__global__ void gate_transpose_kernel(const float* __restrict__ x1,
                                      float* __restrict__ out) {
    __shared__ float tile[32][33];           // [c_local][l_local]
    const int tx = threadIdx.x, ty = threadIdx.y;
    const int c0 = blockIdx.x * 32, l0 = blockIdx.y * 32, b = blockIdx.z;
    const int cp0 = blockIdx.x * 16;
    #pragma unroll
    for (int k = 0; k < 2; k++) {
        int u = ty + k * 8;                  // channel-pair local index
        int l = l0 + tx;
        float2 yv = g_yP[((size_t)(b * CP_ + cp0 + u)) * L_ + l];
        tile[2 * u][tx]     = yv.x;
        tile[2 * u + 1][tx] = yv.y;
    }
    __syncthreads();
    #pragma unroll
    for (int k = 0; k < 4; k++) {
        int l = l0 + ty + k * 8;
        size_t idx = ((size_t)(b * L_ + l)) * D_ + (c0 + tx);
        out[idx] = x1[idx] * tile[tx][ty + k * 8];
    }
}

extern "C" void kernel_launch(void* const* d_in, const int* in_sizes, int n_in,
                              void* d_out, int out_size) {
    const float* x1   = (const float*)d_in[0];
    const float* x2   = (const float*)d_in[1];
    const float* v    = (const float*)d_in[2];
    const float* h    = (const float*)d_in[3];
    const float* bias = (const float*)d_in[4];
    float* out = (float*)d_out;

    cudaFuncSetAttribute(filter_fft_kernel,
                         cudaFuncAttributeMaxDynamicSharedMemorySize, SMEM_BYTES);
    cudaFuncSetAttribute(conv_fft_kernel,
                         cudaFuncAttributeMaxDynamicSharedMemorySize, SMEM_BYTES);

    dim3 tgrid(D_ / 32, L_ / 32, B_);
    dim3 tblk(32, 8);

    twiddle_kernel<<<TWN / 256, 256>>>();
    filter_fft_kernel<<<G_, TPB, SMEM_BYTES>>>(h);
    kv_transpose_kernel<<<tgrid, tblk>>>(x2, v);
    conv_fft_kernel<<<B_ * CP_, TPB, SMEM_BYTES>>>(bias);
    gate_transpose_kernel<<<tgrid, tblk>>>(x1, out);
}

// round 14
// speedup vs baseline: 4.3556x; 1.0825x over previous
#include <cuda_runtime.h>
#include <cuda_bf16.h>
#include <cstdint>

// Shapes
#define B_  2
#define L_  8192
#define G_  256
#define DG_ 8
#define D_  2048          // G_*DG_
#define CP_ (D_/2)        // 1024 channel pairs
#define NFFT 16384        // 2*L_, 4^7
#define NBFLY (NFFT/4)    // 4096
#define NSETS (NFFT/16)   // 1024 fused radix-16 sets per pass
#define TPB 1024
#define TWN  (NFFT/4)     // quarter-circle twiddle table

// skewed smem index: i + 2*(i>>5).
// - keeps consecutive / stride>=32 access conflict-free
// - makes stride-4 quad patterns conflict-free (bank = 4q + j + const)
// - phys(4b) is even and quartets contiguous -> float4-able middle pass
__device__ __forceinline__ int phys(int i) { return i + 2 * (i >> 5); }

#define S_F2   (NFFT + 2*(NFFT/32))        // 17408
#define TW_F2  (TWN + 2*(TWN/32))          // 4352
#define SMEM_F2 (S_F2 + TW_F2)             // 21760
#define SMEM_BYTES (SMEM_F2 * (int)sizeof(float2))  // 174080 B

// scratch (device globals: allocation-free)
__device__ float2 g_kvP[(size_t)B_ * CP_ * L_];   // (B, CP, L) packed kv pairs
__device__ float2 g_yP [(size_t)B_ * CP_ * L_];   // (B, CP, L) packed conv outputs
__device__ float2 g_HF [(size_t)G_ * NFFT];       // per-group filter spectrum (scrambled, /N)
__device__ float2 g_TW [TWN];                     // twiddle master copy

__device__ __forceinline__ float2 cadd(float2 a, float2 b) { return make_float2(a.x + b.x, a.y + b.y); }
__device__ __forceinline__ float2 csub(float2 a, float2 b) { return make_float2(a.x - b.x, a.y - b.y); }
__device__ __forceinline__ float2 cmul(float2 a, float2 b) {
    return make_float2(a.x * b.x - a.y * b.y, a.x * b.y + a.y * b.x);
}
__device__ __forceinline__ float2 conj2(float2 a) { return make_float2(a.x, -a.y); }

// skewed twiddle read
__device__ __forceinline__ float2 twl(const float2* TW, int k) { return TW[k + 2 * (k >> 5)]; }

// K-1: build twiddle table once. TW[k] = e^{-2*pi*i*k/NFFT}
__global__ void twiddle_kernel() {
    int k = blockIdx.x * blockDim.x + threadIdx.x;
    if (k < TWN) {
        float s, c;
        sincospif(-(float)k * (1.0f / (NFFT / 2)), &s, &c);
        g_TW[k] = make_float2(c, s);
    }
}

__device__ __forceinline__ void load_tw(float2* TW, int tid) {
    for (int k = tid; k < TWN; k += TPB) TW[k + 2 * (k >> 5)] = g_TW[k];
}

// ---------------- fused forward: two DIF radix-4 stages (Lc and Lc/4) per smem pass
template <int Lc>
__device__ __forceinline__ void fwd_fused(float2* S, const float2* TW, int tid) {
    const int st   = Lc / 16;
    const int tmul = NFFT / Lc;
    #pragma unroll
    for (int ss = 0; ss < NSETS / TPB; ss++) {
        int s  = tid + ss * TPB;
        int j  = s & (st - 1);
        int i0 = (s / st) * Lc + j;
        float2 x[16];
        #pragma unroll
        for (int m = 0; m < 16; m++) x[m] = S[phys(i0 + m * st)];
        // stage length Lc (span 4*st)
        #pragma unroll
        for (int g = 0; g < 4; g++) {
            float2 a0 = x[g], a1 = x[g + 4], a2 = x[g + 8], a3 = x[g + 12];
            float2 t0 = cadd(a0, a2), t1 = csub(a0, a2);
            float2 t2 = cadd(a1, a3), t3 = csub(a1, a3);
            float2 w1 = twl(TW, (j + g * st) * tmul);
            float2 w2 = cmul(w1, w1), w3 = cmul(w2, w1);
            x[g]      = cadd(t0, t2);
            x[g + 4]  = cmul(make_float2(t1.x + t3.y, t1.y - t3.x), w1);
            x[g + 8]  = cmul(csub(t0, t2), w2);
            x[g + 12] = cmul(make_float2(t1.x - t3.y, t1.y + t3.x), w3);
        }
        // stage length Lc/4 (span st)
        {
            float2 w1 = twl(TW, j * tmul * 4);
            float2 w2 = cmul(w1, w1), w3 = cmul(w2, w1);
            #pragma unroll
            for (int r = 0; r < 4; r++) {
                float2 a0 = x[4 * r], a1 = x[4 * r + 1], a2 = x[4 * r + 2], a3 = x[4 * r + 3];
                float2 t0 = cadd(a0, a2), t1 = csub(a0, a2);
                float2 t2 = cadd(a1, a3), t3 = csub(a1, a3);
                x[4 * r]     = cadd(t0, t2);
                x[4 * r + 1] = cmul(make_float2(t1.x + t3.y, t1.y - t3.x), w1);
                x[4 * r + 2] = cmul(csub(t0, t2), w2);
                x[4 * r + 3] = cmul(make_float2(t1.x - t3.y, t1.y + t3.x), w3);
            }
        }
        #pragma unroll
        for (int m = 0; m < 16; m++) S[phys(i0 + m * st)] = x[m];
    }
}

// first forward pass (stages 16384, 4096) reading x[m] directly from global.
// Input has only NFFT/2 nonzero elements (m<8); upper half implicitly zero.
__device__ __forceinline__ void fwd_first_from_global(float2* S, const float2* TW,
                                                      int tid, const float2* __restrict__ in) {
    const int j = tid;                       // st=1024, tmul=1, one set per thread
    float2 x[16];
    #pragma unroll
    for (int m = 0; m < 8; m++) x[m] = __ldg(&in[j + m * 1024]);
    // stage 16384 with a2=a3=0
    #pragma unroll
    for (int g = 0; g < 4; g++) {
        float2 a0 = x[g], a1 = x[g + 4];
        float2 w1 = twl(TW, j + g * 1024);
        float2 w2 = cmul(w1, w1), w3 = cmul(w2, w1);
        x[g]      = cadd(a0, a1);
        x[g + 4]  = cmul(make_float2(a0.x + a1.y, a0.y - a1.x), w1);   // a0 - i a1
        x[g + 8]  = cmul(csub(a0, a1), w2);
        x[g + 12] = cmul(make_float2(a0.x - a1.y, a0.y + a1.x), w3);   // a0 + i a1
    }
    // stage 4096 (span 1024), twiddle base j*4
    {
        float2 w1 = twl(TW, j * 4);
        float2 w2 = cmul(w1, w1), w3 = cmul(w2, w1);
        #pragma unroll
        for (int r = 0; r < 4; r++) {
            float2 a0 = x[4 * r], a1 = x[4 * r + 1], a2 = x[4 * r + 2], a3 = x[4 * r + 3];
            float2 t0 = cadd(a0, a2), t1 = csub(a0, a2);
            float2 t2 = cadd(a1, a3), t3 = csub(a1, a3);
            x[4 * r]     = cadd(t0, t2);
            x[4 * r + 1] = cmul(make_float2(t1.x + t3.y, t1.y - t3.x), w1);
            x[4 * r + 2] = cmul(csub(t0, t2), w2);
            x[4 * r + 3] = cmul(make_float2(t1.x - t3.y, t1.y + t3.x), w3);
        }
    }
    #pragma unroll
    for (int m = 0; m < 16; m++) S[phys(j + m * 1024)] = x[m];
}

// same, for a real-valued global input (filter h)
__device__ __forceinline__ void fwd_first_from_global_real(float2* S, const float2* TW,
                                                           int tid, const float* __restrict__ in) {
    const int j = tid;
    float2 x[16];
    #pragma unroll
    for (int m = 0; m < 8; m++) x[m] = make_float2(__ldg(&in[j + m * 1024]), 0.0f);
    #pragma unroll
    for (int g = 0; g < 4; g++) {
        float2 a0 = x[g], a1 = x[g + 4];
        float2 w1 = twl(TW, j + g * 1024);
        float2 w2 = cmul(w1, w1), w3 = cmul(w2, w1);
        x[g]      = cadd(a0, a1);
        x[g + 4]  = cmul(make_float2(a0.x + a1.y, a0.y - a1.x), w1);
        x[g + 8]  = cmul(csub(a0, a1), w2);
        x[g + 12] = cmul(make_float2(a0.x - a1.y, a0.y + a1.x), w3);
    }
    {
        float2 w1 = twl(TW, j * 4);
        float2 w2 = cmul(w1, w1), w3 = cmul(w2, w1);
        #pragma unroll
        for (int r = 0; r < 4; r++) {
            float2 a0 = x[4 * r], a1 = x[4 * r + 1], a2 = x[4 * r + 2], a3 = x[4 * r + 3];
            float2 t0 = cadd(a0, a2), t1 = csub(a0, a2);
            float2 t2 = cadd(a1, a3), t3 = csub(a1, a3);
            x[4 * r]     = cadd(t0, t2);
            x[4 * r + 1] = cmul(make_float2(t1.x + t3.y, t1.y - t3.x), w1);
            x[4 * r + 2] = cmul(csub(t0, t2), w2);
            x[4 * r + 3] = cmul(make_float2(t1.x - t3.y, t1.y + t3.x), w3);
        }
    }
    #pragma unroll
    for (int m = 0; m < 16; m++) S[phys(j + m * 1024)] = x[m];
}

// ---------------- fused inverse: two DIT radix-4 stages (l and 4l) per smem pass
template <int l>
__device__ __forceinline__ void inv_fused(float2* S, const float2* TW, int tid) {
    const int st    = l / 4;
    const int tmul  = NFFT / l;
    const int tmul4 = tmul / 4;
    #pragma unroll
    for (int ss = 0; ss < NSETS / TPB; ss++) {
        int s  = tid + ss * TPB;
        int j  = s & (st - 1);
        int i0 = (s / st) * (4 * l) + j;
        float2 x[16];
        #pragma unroll
        for (int m = 0; m < 16; m++) x[m] = S[phys(i0 + m * st)];
        // stage l (span st)
        {
            float2 w1 = conj2(twl(TW, j * tmul));
            float2 w2 = cmul(w1, w1), w3 = cmul(w2, w1);
            #pragma unroll
            for (int r = 0; r < 4; r++) {
                float2 a0 = x[4 * r], a1 = x[4 * r + 1], a2 = x[4 * r + 2], a3 = x[4 * r + 3];
                float2 d1 = cmul(a1, w1), d2 = cmul(a2, w2), d3 = cmul(a3, w3);
                float2 u0 = cadd(a0, d2), u1 = csub(a0, d2);
                float2 u2 = cadd(d1, d3), u3 = csub(d1, d3);
                x[4 * r]     = cadd(u0, u2);
                x[4 * r + 1] = make_float2(u1.x - u3.y, u1.y + u3.x);
                x[4 * r + 2] = csub(u0, u2);
                x[4 * r + 3] = make_float2(u1.x + u3.y, u1.y - u3.x);
            }
        }
        // stage 4l (span 4*st)
        #pragma unroll
        for (int g = 0; g < 4; g++) {
            float2 w1 = conj2(twl(TW, (j + g * st) * tmul4));
            float2 w2 = cmul(w1, w1), w3 = cmul(w2, w1);
            float2 a0 = x[g], a1 = x[g + 4], a2 = x[g + 8], a3 = x[g + 12];
            float2 d1 = cmul(a1, w1), d2 = cmul(a2, w2), d3 = cmul(a3, w3);
            float2 u0 = cadd(a0, d2), u1 = csub(a0, d2);
            float2 u2 = cadd(d1, d3), u3 = csub(d1, d3);
            x[g]      = cadd(u0, u2);
            x[g + 4]  = make_float2(u1.x - u3.y, u1.y + u3.x);
            x[g + 8]  = csub(u0, u2);
            x[g + 12] = make_float2(u1.x + u3.y, u1.y - u3.x);
        }
        #pragma unroll
        for (int m = 0; m < 16; m++) S[phys(i0 + m * st)] = x[m];
    }
}

// last inverse pass (stages 4096, 16384) writing results + bias directly to global.
__device__ __forceinline__ void inv_last_to_global(const float2* S, const float2* TW, int tid,
                                                   const float2* __restrict__ kv,
                                                   float2* __restrict__ out,
                                                   float bias0, float bias1) {
    const int j = tid;
    float2 x[16];
    #pragma unroll
    for (int m = 0; m < 16; m++) x[m] = S[phys(j + m * 1024)];
    // stage 4096 (span 1024), twiddle base j*4
    {
        float2 w1 = conj2(twl(TW, j * 4));
        float2 w2 = cmul(w1, w1), w3 = cmul(w2, w1);
        #pragma unroll
        for (int r = 0; r < 4; r++) {
            float2 a0 = x[4 * r], a1 = x[4 * r + 1], a2 = x[4 * r + 2], a3 = x[4 * r + 3];
            float2 d1 = cmul(a1, w1), d2 = cmul(a2, w2), d3 = cmul(a3, w3);
            float2 u0 = cadd(a0, d2), u1 = csub(a0, d2);
            float2 u2 = cadd(d1, d3), u3 = csub(d1, d3);
            x[4 * r]     = cadd(u0, u2);
            x[4 * r + 1] = make_float2(u1.x - u3.y, u1.y + u3.x);
            x[4 * r + 2] = csub(u0, u2);
            x[4 * r + 3] = make_float2(u1.x + u3.y, u1.y - u3.x);
        }
    }
    // stage 16384: only outputs with i < L_ are kept
    float2 y[8];
    #pragma unroll
    for (int g = 0; g < 4; g++) {
        float2 w1 = conj2(twl(TW, j + g * 1024));
        float2 w2 = cmul(w1, w1), w3 = cmul(w2, w1);
        float2 a0 = x[g], a1 = x[g + 4], a2 = x[g + 8], a3 = x[g + 12];
        float2 d1 = cmul(a1, w1), d2 = cmul(a2, w2), d3 = cmul(a3, w3);
        float2 u0 = cadd(a0, d2), u1 = csub(a0, d2);
        float2 u2 = cadd(d1, d3), u3 = csub(d1, d3);
        y[g]     = cadd(u0, u2);
        y[g + 4] = make_float2(u1.x - u3.y, u1.y + u3.x);
    }
    #pragma unroll
    for (int m = 0; m < 8; m++) {
        int i = j + m * 1024;
        float2 k2 = __ldg(&kv[i]);
        out[i] = make_float2(y[m].x + k2.x * bias0, y[m].y + k2.y * bias1);
    }
}

// K0: filter spectrum per group. grid = G_, block = TPB
__global__ void __launch_bounds__(TPB, 1)
filter_fft_kernel(const float* __restrict__ h) {
    extern __shared__ float2 smem[];
    float2* S  = smem;
    float2* TW = smem + S_F2;
    const int tid = threadIdx.x;
    const int g = blockIdx.x;
    load_tw(TW, tid);
    __syncthreads();
    fwd_first_from_global_real(S, TW, tid, h + (size_t)g * L_);
    __syncthreads();
    fwd_fused<1024>(S, TW, tid); __syncthreads();
    fwd_fused<64>(S, TW, tid);   __syncthreads();
    // final length-4 DIF stage fused with the scaled writeout (float4 smem loads)
    const float sc = 1.0f / (float)NFFT;
    float2* out = g_HF + (size_t)g * NFFT;
    const float4* S4 = (const float4*)S;
    #pragma unroll
    for (int k = 0; k < NBFLY / TPB; k++) {
        int b = tid + k * TPB;
        int i0 = 4 * b;
        int q  = phys(i0) >> 1;              // float4 index (phys(i0) even, quartet contiguous)
        float4 p01 = S4[q], p23 = S4[q + 1];
        float2 a0 = make_float2(p01.x, p01.y), a1 = make_float2(p01.z, p01.w);
        float2 a2 = make_float2(p23.x, p23.y), a3 = make_float2(p23.z, p23.w);
        float2 t0 = cadd(a0, a2), t1 = csub(a0, a2);
        float2 t2 = cadd(a1, a3), t3 = csub(a1, a3);
        float2 y0 = cadd(t0, t2);
        float2 y1 = make_float2(t1.x + t3.y, t1.y - t3.x);
        float2 y2 = csub(t0, t2);
        float2 y3 = make_float2(t1.x - t3.y, t1.y + t3.x);
        float4* o4 = (float4*)(out + i0);
        o4[0] = make_float4(y0.x * sc, y0.y * sc, y1.x * sc, y1.y * sc);
        o4[1] = make_float4(y2.x * sc, y2.y * sc, y3.x * sc, y3.y * sc);
    }
}

// K1: kvP[b,cp,l] = (kv[2cp], kv[2cp+1]) with kv = x2*v.
// grid (D/32, L/32, B), block (32,8)
__global__ void kv_transpose_kernel(const float* __restrict__ x2,
                                    const float* __restrict__ v) {
    __shared__ float tile[32][33];           // [l_local][c_local]
    const int tx = threadIdx.x, ty = threadIdx.y;
    const int c0 = blockIdx.x * 32, l0 = blockIdx.y * 32, b = blockIdx.z;
    #pragma unroll
    for (int k = 0; k < 4; k++) {
        int l = l0 + ty + k * 8;
        size_t idx = ((size_t)(b * L_ + l)) * D_ + (c0 + tx);
        tile[ty + k * 8][tx] = x2[idx] * v[idx];
    }
    __syncthreads();
    const int cp0 = blockIdx.x * 16;
    #pragma unroll
    for (int k = 0; k < 2; k++) {
        int u = ty + k * 8;
        int l = l0 + tx;
        float2 pr = make_float2(tile[tx][2 * u], tile[tx][2 * u + 1]);
        g_kvP[((size_t)(b * CP_ + cp0 + u)) * L_ + l] = pr;
    }
}

// K2: per (b, channel-pair) packed FFT convolution + bias. grid = B*CP_, block = TPB
__global__ void __launch_bounds__(TPB, 1)
conv_fft_kernel(const float* __restrict__ conv_bias) {
    extern __shared__ float2 smem[];
    float2* S  = smem;
    float2* TW = smem + S_F2;
    const int tid = threadIdx.x;
    const int row = blockIdx.x;              // = b*CP_ + cp
    const int cp  = row & (CP_ - 1);
    const int c0  = cp * 2;
    const int g   = c0 >> 3;
    load_tw(TW, tid);
    __syncthreads();
    const float2* kv = g_kvP + (size_t)row * L_;
    fwd_first_from_global(S, TW, tid, kv);
    __syncthreads();
    fwd_fused<1024>(S, TW, tid); __syncthreads();
    fwd_fused<64>(S, TW, tid);   __syncthreads();
    // fused middle: final fwd length-4 stage + pointwise *HF + first inv length-4 stage
    // all float4 accesses (phys(4b) even, quartets contiguous, conflict-free)
    const float2* HF = g_HF + (size_t)g * NFFT;
    float4* S4 = (float4*)S;
    #pragma unroll
    for (int k = 0; k < NBFLY / TPB; k++) {
        int b = tid + k * TPB;
        int i0 = 4 * b;
        int q  = phys(i0) >> 1;
        float4 p01 = S4[q], p23 = S4[q + 1];
        float2 a0 = make_float2(p01.x, p01.y), a1 = make_float2(p01.z, p01.w);
        float2 a2 = make_float2(p23.x, p23.y), a3 = make_float2(p23.z, p23.w);
        // forward length-4 butterfly
        float2 t0 = cadd(a0, a2), t1 = csub(a0, a2);
        float2 t2 = cadd(a1, a3), t3 = csub(a1, a3);
        float2 y0 = cadd(t0, t2);
        float2 y1 = make_float2(t1.x + t3.y, t1.y - t3.x);
        float2 y2 = csub(t0, t2);
        float2 y3 = make_float2(t1.x - t3.y, t1.y + t3.x);
        // pointwise multiply by filter spectrum (vectorized global loads)
        const float4* h4 = (const float4*)(HF + i0);
        float4 hA = __ldg(&h4[0]), hB = __ldg(&h4[1]);
        y0 = cmul(y0, make_float2(hA.x, hA.y));
        y1 = cmul(y1, make_float2(hA.z, hA.w));
        y2 = cmul(y2, make_float2(hB.x, hB.y));
        y3 = cmul(y3, make_float2(hB.z, hB.w));
        // inverse length-4 butterfly
        float2 u0 = cadd(y0, y2), u1 = csub(y0, y2);
        float2 u2 = cadd(y1, y3), u3 = csub(y1, y3);
        float2 r0 = cadd(u0, u2);
        float2 r1 = make_float2(u1.x - u3.y, u1.y + u3.x);
        float2 r2 = csub(u0, u2);
        float2 r3 = make_float2(u1.x + u3.y, u1.y - u3.x);
        S4[q]     = make_float4(r0.x, r0.y, r1.x, r1.y);
        S4[q + 1] = make_float4(r2.x, r2.y, r3.x, r3.y);
    }
    __syncthreads();
    inv_fused<16>(S, TW, tid);  __syncthreads();
    inv_fused<256>(S, TW, tid); __syncthreads();
    inv_last_to_global(S, TW, tid, kv, g_yP + (size_t)row * L_,
                       conv_bias[c0], conv_bias[c0 + 1]);
}

// K3: out[b,l,c] = x1[b,l,c] * y[b,c,l]. grid (D/32, L/32, B), block (32,8)
__global__ void gate_transpose_kernel(const float* __restrict__ x1,
                                      float* __restrict__ out) {
    __shared__ float tile[32][33];           // [c_local][l_local]
    const int tx = threadIdx.x, ty = threadIdx.y;
    const int c0 = blockIdx.x * 32, l0 = blockIdx.y * 32, b = blockIdx.z;
    const int cp0 = blockIdx.x * 16;
    #pragma unroll
    for (int k = 0; k < 2; k++) {
        int u = ty + k * 8;
        int l = l0 + tx;
        float2 yv = g_yP[((size_t)(b * CP_ + cp0 + u)) * L_ + l];
        tile[2 * u][tx]     = yv.x;
        tile[2 * u + 1][tx] = yv.y;
    }
    __syncthreads();
    #pragma unroll
    for (int k = 0; k < 4; k++) {
        int l = l0 + ty + k * 8;
        size_t idx = ((size_t)(b * L_ + l)) * D_ + (c0 + tx);
        out[idx] = x1[idx] * tile[tx][ty + k * 8];
    }
}

extern "C" void kernel_launch(void* const* d_in, const int* in_sizes, int n_in,
                              void* d_out, int out_size) {
    const float* x1   = (const float*)d_in[0];
    const float* x2   = (const float*)d_in[1];
    const float* v    = (const float*)d_in[2];
    const float* h    = (const float*)d_in[3];
    const float* bias = (const float*)d_in[4];
    float* out = (float*)d_out;

    cudaFuncSetAttribute(filter_fft_kernel,
                         cudaFuncAttributeMaxDynamicSharedMemorySize, SMEM_BYTES);
    cudaFuncSetAttribute(conv_fft_kernel,
                         cudaFuncAttributeMaxDynamicSharedMemorySize, SMEM_BYTES);

    dim3 tgrid(D_ / 32, L_ / 32, B_);
    dim3 tblk(32, 8);

    twiddle_kernel<<<TWN / 256, 256>>>();
    filter_fft_kernel<<<G_, TPB, SMEM_BYTES>>>(h);
    kv_transpose_kernel<<<tgrid, tblk>>>(x2, v);
    conv_fft_kernel<<<B_ * CP_, TPB, SMEM_BYTES>>>(bias);
    gate_transpose_kernel<<<tgrid, tblk>>>(x1, out);
}